// round 2
// baseline (speedup 1.0000x reference)
#include <cuda_runtime.h>
#include <cuda_bf16.h>
#include <math_constants.h>

#define N_NODES 50000
#define N_EDGES 800000
#define D 128
#define N_GRAPHS 64

// ------------------------- device scratch (static; no runtime alloc) -------
__device__ float g_dis[N_NODES];            // deg^{-1/2} on (A+I)
__device__ int   g_deg[N_NODES];
__device__ int   g_rowoff[N_NODES + 1];     // CSR row offsets (by dst)
__device__ int   g_fill[N_NODES];
__device__ int   g_col[N_EDGES];            // src per CSR slot
__device__ float g_w[N_EDGES];              // dis[src]*dis[dst] per CSR slot
__device__ float g_h[N_NODES * D];          // x @ W
__device__ float g_agg[N_NODES * D];        // aggregated output of a layer
__device__ int   g_gstart[N_GRAPHS + 1];    // graph boundaries in sorted batch

// ------------------------- CSR build ---------------------------------------
__global__ void k_zero() {
    int i = blockIdx.x * blockDim.x + threadIdx.x;
    if (i < N_NODES) { g_deg[i] = 0; g_fill[i] = 0; }
}

__global__ void k_count(const int* __restrict__ dst) {
    int i = blockIdx.x * blockDim.x + threadIdx.x;
    if (i < N_EDGES) atomicAdd(&g_deg[dst[i]], 1);
}

// single-block exclusive scan of g_deg -> g_rowoff, plus deg_inv_sqrt
__global__ void k_scan() {
    __shared__ int s[1024];
    __shared__ int carry;
    int t = threadIdx.x;
    if (t == 0) carry = 0;
    __syncthreads();
    for (int base = 0; base < N_NODES; base += 1024) {
        int i = base + t;
        int v = (i < N_NODES) ? g_deg[i] : 0;
        s[t] = v;
        __syncthreads();
        for (int off = 1; off < 1024; off <<= 1) {
            int add = (t >= off) ? s[t - off] : 0;
            __syncthreads();
            s[t] += add;
            __syncthreads();
        }
        if (i < N_NODES) {
            g_rowoff[i] = carry + s[t] - v;            // exclusive
            g_dis[i] = rsqrtf((float)v + 1.0f);        // deg on A+I
        }
        int total = s[1023];
        __syncthreads();
        if (t == 0) carry += total;
        __syncthreads();
    }
    if (t == 0) g_rowoff[N_NODES] = carry;
}

__global__ void k_fill(const int* __restrict__ src, const int* __restrict__ dst) {
    int i = blockIdx.x * blockDim.x + threadIdx.x;
    if (i < N_EDGES) {
        int d = dst[i], s = src[i];
        int pos = g_rowoff[d] + atomicAdd(&g_fill[d], 1);
        g_col[pos] = s;
        g_w[pos] = g_dis[s] * g_dis[d];
    }
}

// graph boundaries: g_gstart[g] = lower_bound(batch, g)
__global__ void k_gstart(const int* __restrict__ batch) {
    int g = threadIdx.x;
    if (g > N_GRAPHS) return;
    int lo = 0, hi = N_NODES;
    while (lo < hi) {
        int mid = (lo + hi) >> 1;
        if (batch[mid] < g) lo = mid + 1; else hi = mid;
    }
    g_gstart[g] = lo;
}

// ------------------------- GEMM: H = A @ W  (A: [N,128], W: [128,128]) -----
// block: 256 threads = 16x16, tile 64 rows x 128 cols, k-chunks of 32
__global__ __launch_bounds__(256) void k_gemm(const float* __restrict__ A,
                                              const float* __restrict__ Wm,
                                              float* __restrict__ Hout) {
    __shared__ float Ws[32][128];
    __shared__ float xs[64][33];           // +1 pad: conflict-free a-loads
    int tid = threadIdx.x;
    int tx = tid & 15, ty = tid >> 4;
    int row0 = blockIdx.x * 64;
    float acc[4][8];
#pragma unroll
    for (int i = 0; i < 4; i++)
#pragma unroll
        for (int j = 0; j < 8; j++) acc[i][j] = 0.0f;

    for (int kc = 0; kc < 128; kc += 32) {
        // W chunk: contiguous 32*128 floats
        const float4* Wg = (const float4*)(Wm + kc * 128);
        float4* Ws4 = (float4*)&Ws[0][0];
#pragma unroll
        for (int i = tid; i < 1024; i += 256) Ws4[i] = Wg[i];
        // A chunk: 64 rows x 32 cols
#pragma unroll
        for (int i = tid; i < 512; i += 256) {
            int r = i >> 3;
            int kq = (i & 7) * 4;
            float4 v = make_float4(0.f, 0.f, 0.f, 0.f);
            if (row0 + r < N_NODES)
                v = *(const float4*)(A + (size_t)(row0 + r) * D + kc + kq);
            xs[r][kq + 0] = v.x; xs[r][kq + 1] = v.y;
            xs[r][kq + 2] = v.z; xs[r][kq + 3] = v.w;
        }
        __syncthreads();
#pragma unroll
        for (int k = 0; k < 32; k++) {
            float a0 = xs[ty * 4 + 0][k];
            float a1 = xs[ty * 4 + 1][k];
            float a2 = xs[ty * 4 + 2][k];
            float a3 = xs[ty * 4 + 3][k];
            float b[8];
#pragma unroll
            for (int j = 0; j < 8; j++) b[j] = Ws[k][tx * 8 + j];
#pragma unroll
            for (int j = 0; j < 8; j++) {
                acc[0][j] += a0 * b[j];
                acc[1][j] += a1 * b[j];
                acc[2][j] += a2 * b[j];
                acc[3][j] += a3 * b[j];
            }
        }
        __syncthreads();
    }
#pragma unroll
    for (int i = 0; i < 4; i++) {
        int r = row0 + ty * 4 + i;
        if (r < N_NODES) {
            float4* o = (float4*)(Hout + (size_t)r * D + tx * 8);
            o[0] = make_float4(acc[i][0], acc[i][1], acc[i][2], acc[i][3]);
            o[1] = make_float4(acc[i][4], acc[i][5], acc[i][6], acc[i][7]);
        }
    }
}

// ------------------------- aggregation: one warp per node ------------------
// out[i] = sum_e w_e * h[col_e] + dis[i]^2 * h[i] + b  (optional ReLU)
__global__ __launch_bounds__(256) void k_agg(const float* __restrict__ h,
                                             const float* __restrict__ b,
                                             float* __restrict__ out,
                                             int do_relu) {
    int lane = threadIdx.x & 31;
    int node = blockIdx.x * (blockDim.x >> 5) + (threadIdx.x >> 5);
    if (node >= N_NODES) return;
    int beg = g_rowoff[node], end = g_rowoff[node + 1];
    const float4* __restrict__ h4 = (const float4*)h;
    float4 acc = make_float4(0.f, 0.f, 0.f, 0.f);
    for (int e0 = beg; e0 < end; e0 += 32) {
        int n = min(32, end - e0);
        int c = 0; float wv = 0.f;
        if (lane < n) { c = g_col[e0 + lane]; wv = g_w[e0 + lane]; }
        for (int j = 0; j < n; j++) {
            int cj = __shfl_sync(0xffffffffu, c, j);
            float wj = __shfl_sync(0xffffffffu, wv, j);
            float4 hv = h4[(size_t)cj * 32 + lane];
            acc.x += wj * hv.x; acc.y += wj * hv.y;
            acc.z += wj * hv.z; acc.w += wj * hv.w;
        }
    }
    float dis = g_dis[node];
    float sw = dis * dis;
    float4 hs = h4[(size_t)node * 32 + lane];
    acc.x += sw * hs.x; acc.y += sw * hs.y;
    acc.z += sw * hs.z; acc.w += sw * hs.w;
    float4 bv = ((const float4*)b)[lane];
    acc.x += bv.x; acc.y += bv.y; acc.z += bv.z; acc.w += bv.w;
    if (do_relu) {
        acc.x = fmaxf(acc.x, 0.f); acc.y = fmaxf(acc.y, 0.f);
        acc.z = fmaxf(acc.z, 0.f); acc.w = fmaxf(acc.w, 0.f);
    }
    ((float4*)out)[(size_t)node * 32 + lane] = acc;
}

// ------------------------- global max pool ---------------------------------
__global__ void k_pool(float* __restrict__ out) {
    int g = blockIdx.x;
    int t = threadIdx.x;             // 128 = D
    int beg = g_gstart[g], end = g_gstart[g + 1];
    float m = -CUDART_INF_F;
    for (int r = beg; r < end; r++)
        m = fmaxf(m, g_agg[(size_t)r * D + t]);
    out[(size_t)g * D + t] = m;
}

// ------------------------- launch ------------------------------------------
extern "C" void kernel_launch(void* const* d_in, const int* in_sizes, int n_in,
                              void* d_out, int out_size) {
    const float* x  = (const float*)d_in[0];
    const float* W1 = (const float*)d_in[1];
    const float* b1 = (const float*)d_in[2];
    const float* W2 = (const float*)d_in[3];
    const float* b2 = (const float*)d_in[4];
    const float* W3 = (const float*)d_in[5];
    const float* b3 = (const float*)d_in[6];
    const int* edge_index = (const int*)d_in[7];
    const int* batch = (const int*)d_in[8];
    const int* src = edge_index;
    const int* dst = edge_index + N_EDGES;
    float* out = (float*)d_out;

    float* h   = nullptr; cudaGetSymbolAddress((void**)&h,   g_h);
    float* agg = nullptr; cudaGetSymbolAddress((void**)&agg, g_agg);

    const int nthr = 256;
    // CSR build
    k_zero  <<<(N_NODES + nthr - 1) / nthr, nthr>>>();
    k_count <<<(N_EDGES + nthr - 1) / nthr, nthr>>>(dst);
    k_scan  <<<1, 1024>>>();
    k_fill  <<<(N_EDGES + nthr - 1) / nthr, nthr>>>(src, dst);
    k_gstart<<<1, N_GRAPHS + 1>>>(batch);

    const int gemm_grid = (N_NODES + 63) / 64;
    const int agg_grid  = (N_NODES + 7) / 8;   // 8 warps/block

    // layer 1
    k_gemm<<<gemm_grid, 256>>>(x, W1, h);
    k_agg <<<agg_grid, 256>>>(h, b1, agg, 1);
    // layer 2
    k_gemm<<<gemm_grid, 256>>>(agg, W2, h);
    k_agg <<<agg_grid, 256>>>(h, b2, agg, 1);
    // layer 3
    k_gemm<<<gemm_grid, 256>>>(agg, W3, h);
    k_agg <<<agg_grid, 256>>>(h, b3, agg, 0);
    // pool
    k_pool<<<N_GRAPHS, D>>>(out);
}

// round 4
// speedup vs baseline: 1.5542x; 1.5542x over previous
#include <cuda_runtime.h>
#include <cuda_bf16.h>
#include <math_constants.h>
#include <cstdint>

#define N_NODES 50000
#define N_EDGES 800000
#define D 128
#define N_GRAPHS 64
#define SCAN_BLK 1024
#define N_SCAN_BLKS ((N_NODES + SCAN_BLK - 1) / SCAN_BLK)   // 49
#define POOL_CHUNKS 8

// ------------------------- device scratch ----------------------------------
__device__ float g_dis[N_NODES];
__device__ int   g_deg[N_NODES];
__device__ int   g_rowoff[N_NODES + 1];
__device__ int   g_next[N_NODES];
__device__ int   g_bsum[N_SCAN_BLKS];
__device__ int   g_boff[N_SCAN_BLKS];
__device__ int   g_col[N_EDGES];
__device__ float g_w[N_EDGES];
__device__ float g_h[N_NODES * D];
__device__ float g_agg[N_NODES * D];
__device__ int   g_gstart[N_GRAPHS + 1];
__device__ float g_pmax[N_GRAPHS * POOL_CHUNKS * D];

// ------------------------- CSR build ---------------------------------------
__global__ void k_zero() {
    int i = blockIdx.x * blockDim.x + threadIdx.x;
    if (i < N_NODES) g_deg[i] = 0;
}

__global__ void k_count(const int* __restrict__ dst) {
    int i = blockIdx.x * blockDim.x + threadIdx.x;
    if (i < N_EDGES) atomicAdd(&g_deg[dst[i]], 1);
}

// local block scan (exclusive, no global offset) + block sums + deg_inv_sqrt
__global__ void k_scan1() {
    __shared__ int s[SCAN_BLK];
    int t = threadIdx.x;
    int i = blockIdx.x * SCAN_BLK + t;
    int v = (i < N_NODES) ? g_deg[i] : 0;
    s[t] = v;
    __syncthreads();
    for (int off = 1; off < SCAN_BLK; off <<= 1) {
        int add = (t >= off) ? s[t - off] : 0;
        __syncthreads();
        s[t] += add;
        __syncthreads();
    }
    if (i < N_NODES) {
        g_rowoff[i] = s[t] - v;
        g_dis[i] = rsqrtf((float)v + 1.0f);
    }
    if (t == SCAN_BLK - 1) g_bsum[blockIdx.x] = s[t];
}

// scan of 49 block sums (single small block)
__global__ void k_scan2() {
    __shared__ int s[64];
    int t = threadIdx.x;
    int v = (t < N_SCAN_BLKS) ? g_bsum[t] : 0;
    s[t] = v;
    __syncthreads();
    for (int off = 1; off < 64; off <<= 1) {
        int add = (t >= off) ? s[t - off] : 0;
        __syncthreads();
        s[t] += add;
        __syncthreads();
    }
    if (t < N_SCAN_BLKS) g_boff[t] = s[t] - v;
}

// add block offsets; init atomic slot counters
__global__ void k_scan3() {
    int t = threadIdx.x;
    int i = blockIdx.x * SCAN_BLK + t;
    if (i < N_NODES) {
        int fin = g_rowoff[i] + g_boff[blockIdx.x];
        g_rowoff[i] = fin;
        g_next[i] = fin;
    }
    if (i == 0) g_rowoff[N_NODES] = N_EDGES;
}

__global__ void k_fill(const int* __restrict__ src, const int* __restrict__ dst) {
    int i = blockIdx.x * blockDim.x + threadIdx.x;
    if (i < N_EDGES) {
        int d = dst[i], s = src[i];
        int pos = atomicAdd(&g_next[d], 1);
        g_col[pos] = s;
        g_w[pos] = g_dis[s] * g_dis[d];
    }
}

__global__ void k_gstart(const int* __restrict__ batch) {
    int g = threadIdx.x;
    if (g > N_GRAPHS) return;
    int lo = 0, hi = N_NODES;
    while (lo < hi) {
        int mid = (lo + hi) >> 1;
        if (batch[mid] < g) lo = mid + 1; else hi = mid;
    }
    g_gstart[g] = lo;
}

// ------------------------- tensor-core GEMM (3xTF32) -----------------------
__device__ __forceinline__ void split_tf32(float x, float& hi, float& lo) {
    uint32_t u;
    asm("cvt.rna.tf32.f32 %0, %1;" : "=r"(u) : "f"(x));
    hi = __uint_as_float(u);
    float r = x - hi;
    asm("cvt.rna.tf32.f32 %0, %1;" : "=r"(u) : "f"(r));
    lo = __uint_as_float(u);
}

#define MMA_TF32(C, A0, A1, A2, A3, B0, B1)                                   \
    asm volatile(                                                             \
        "mma.sync.aligned.m16n8k8.row.col.f32.tf32.tf32.f32 "                 \
        "{%0,%1,%2,%3}, {%4,%5,%6,%7}, {%8,%9}, {%0,%1,%2,%3};"               \
        : "+f"(C[0]), "+f"(C[1]), "+f"(C[2]), "+f"(C[3])                      \
        : "r"(A0), "r"(A1), "r"(A2), "r"(A3), "r"(B0), "r"(B1))

// block: 256 threads (8 warps), M-tile = 128 rows, N = 128, K chunked by 16
__global__ __launch_bounds__(256) void k_gemm_tc(const float* __restrict__ A,
                                                 const float* __restrict__ Wm,
                                                 float* __restrict__ Hout) {
    __shared__ float Ah[128][20], Al[128][20];     // stride 20: conflict-free frags
    __shared__ float Wh[16][132], Wl[16][132];     // stride 132
    int tid  = threadIdx.x;
    int warp = tid >> 5, lane = tid & 31;
    int g = lane >> 2, tg = lane & 3;
    int row0 = blockIdx.x * 128;
    int wrow = warp * 16;

    float acc[16][4];
#pragma unroll
    for (int n = 0; n < 16; n++)
#pragma unroll
        for (int c = 0; c < 4; c++) acc[n][c] = 0.0f;

    for (int kc = 0; kc < 128; kc += 16) {
        // W chunk: 16 x 128  (512 float4, 2 per thread)
#pragma unroll
        for (int i = tid; i < 512; i += 256) {
            int r  = i >> 5;
            int c4 = (i & 31) * 4;
            float4 v = *(const float4*)(Wm + (size_t)(kc + r) * 128 + c4);
            float4 h4, l4;
            split_tf32(v.x, h4.x, l4.x); split_tf32(v.y, h4.y, l4.y);
            split_tf32(v.z, h4.z, l4.z); split_tf32(v.w, h4.w, l4.w);
            *(float4*)&Wh[r][c4] = h4;
            *(float4*)&Wl[r][c4] = l4;
        }
        // A chunk: 128 x 16  (512 float4, 2 per thread)
#pragma unroll
        for (int i = tid; i < 512; i += 256) {
            int r  = i >> 2;
            int c4 = (i & 3) * 4;
            int gr = row0 + r;
            float4 v = make_float4(0.f, 0.f, 0.f, 0.f);
            if (gr < N_NODES)
                v = *(const float4*)(A + (size_t)gr * 128 + kc + c4);
            float4 h4, l4;
            split_tf32(v.x, h4.x, l4.x); split_tf32(v.y, h4.y, l4.y);
            split_tf32(v.z, h4.z, l4.z); split_tf32(v.w, h4.w, l4.w);
            *(float4*)&Ah[r][c4] = h4;
            *(float4*)&Al[r][c4] = l4;
        }
        __syncthreads();

#pragma unroll
        for (int ks = 0; ks < 16; ks += 8) {
            uint32_t ah0 = __float_as_uint(Ah[wrow + g    ][ks + tg    ]);
            uint32_t ah1 = __float_as_uint(Ah[wrow + g + 8][ks + tg    ]);
            uint32_t ah2 = __float_as_uint(Ah[wrow + g    ][ks + tg + 4]);
            uint32_t ah3 = __float_as_uint(Ah[wrow + g + 8][ks + tg + 4]);
            uint32_t al0 = __float_as_uint(Al[wrow + g    ][ks + tg    ]);
            uint32_t al1 = __float_as_uint(Al[wrow + g + 8][ks + tg    ]);
            uint32_t al2 = __float_as_uint(Al[wrow + g    ][ks + tg + 4]);
            uint32_t al3 = __float_as_uint(Al[wrow + g + 8][ks + tg + 4]);
#pragma unroll
            for (int nt = 0; nt < 16; nt++) {
                int n0 = nt * 8;
                uint32_t bh0 = __float_as_uint(Wh[ks + tg    ][n0 + g]);
                uint32_t bh1 = __float_as_uint(Wh[ks + tg + 4][n0 + g]);
                uint32_t bl0 = __float_as_uint(Wl[ks + tg    ][n0 + g]);
                uint32_t bl1 = __float_as_uint(Wl[ks + tg + 4][n0 + g]);
                MMA_TF32(acc[nt], ah0, ah1, ah2, ah3, bh0, bh1);
                MMA_TF32(acc[nt], ah0, ah1, ah2, ah3, bl0, bl1);
                MMA_TF32(acc[nt], al0, al1, al2, al3, bh0, bh1);
            }
        }
        __syncthreads();
    }

    // store: per n-tile rows wrow+g and wrow+g+8, cols n0 + 2*tg (+1)
    int r0 = row0 + wrow + g;
    int r1 = r0 + 8;
#pragma unroll
    for (int nt = 0; nt < 16; nt++) {
        int c0 = nt * 8 + tg * 2;
        if (r0 < N_NODES)
            *(float2*)(Hout + (size_t)r0 * 128 + c0) = make_float2(acc[nt][0], acc[nt][1]);
        if (r1 < N_NODES)
            *(float2*)(Hout + (size_t)r1 * 128 + c0) = make_float2(acc[nt][2], acc[nt][3]);
    }
}

// ------------------------- aggregation: one warp per node ------------------
__global__ __launch_bounds__(256) void k_agg(const float* __restrict__ h,
                                             const float* __restrict__ b,
                                             float* __restrict__ out,
                                             int do_relu) {
    int lane = threadIdx.x & 31;
    int node = blockIdx.x * (blockDim.x >> 5) + (threadIdx.x >> 5);
    if (node >= N_NODES) return;
    int beg = g_rowoff[node], end = g_rowoff[node + 1];
    const float4* __restrict__ h4 = (const float4*)h;
    float4 acc = make_float4(0.f, 0.f, 0.f, 0.f);
    for (int e0 = beg; e0 < end; e0 += 32) {
        int n = min(32, end - e0);
        int c = 0; float wv = 0.f;
        if (lane < n) { c = g_col[e0 + lane]; wv = g_w[e0 + lane]; }
        for (int j = 0; j < n; j++) {
            int cj = __shfl_sync(0xffffffffu, c, j);
            float wj = __shfl_sync(0xffffffffu, wv, j);
            float4 hv = h4[(size_t)cj * 32 + lane];
            acc.x += wj * hv.x; acc.y += wj * hv.y;
            acc.z += wj * hv.z; acc.w += wj * hv.w;
        }
    }
    float dis = g_dis[node];
    float sw = dis * dis;
    float4 hs = h4[(size_t)node * 32 + lane];
    acc.x += sw * hs.x; acc.y += sw * hs.y;
    acc.z += sw * hs.z; acc.w += sw * hs.w;
    float4 bv = ((const float4*)b)[lane];
    acc.x += bv.x; acc.y += bv.y; acc.z += bv.z; acc.w += bv.w;
    if (do_relu) {
        acc.x = fmaxf(acc.x, 0.f); acc.y = fmaxf(acc.y, 0.f);
        acc.z = fmaxf(acc.z, 0.f); acc.w = fmaxf(acc.w, 0.f);
    }
    ((float4*)out)[(size_t)node * 32 + lane] = acc;
}

// ------------------------- pooling -----------------------------------------
__global__ void k_pool1() {
    int g = blockIdx.x, c = blockIdx.y, t = threadIdx.x;
    int beg = g_gstart[g], end = g_gstart[g + 1];
    int len = end - beg;
    int chunk = (len + POOL_CHUNKS - 1) / POOL_CHUNKS;
    int s = beg + c * chunk;
    int e = min(end, s + chunk);
    float m = -CUDART_INF_F;
    for (int r = s; r < e; r++)
        m = fmaxf(m, g_agg[(size_t)r * D + t]);
    g_pmax[(size_t)(g * POOL_CHUNKS + c) * D + t] = m;
}

__global__ void k_pool2(float* __restrict__ out) {
    int g = blockIdx.x, t = threadIdx.x;
    float m = -CUDART_INF_F;
#pragma unroll
    for (int c = 0; c < POOL_CHUNKS; c++)
        m = fmaxf(m, g_pmax[(size_t)(g * POOL_CHUNKS + c) * D + t]);
    out[(size_t)g * D + t] = m;
}

// ------------------------- launch ------------------------------------------
extern "C" void kernel_launch(void* const* d_in, const int* in_sizes, int n_in,
                              void* d_out, int out_size) {
    const float* x  = (const float*)d_in[0];
    const float* W1 = (const float*)d_in[1];
    const float* b1 = (const float*)d_in[2];
    const float* W2 = (const float*)d_in[3];
    const float* b2 = (const float*)d_in[4];
    const float* W3 = (const float*)d_in[5];
    const float* b3 = (const float*)d_in[6];
    const int* edge_index = (const int*)d_in[7];
    const int* batch = (const int*)d_in[8];
    const int* src = edge_index;
    const int* dst = edge_index + N_EDGES;
    float* out = (float*)d_out;

    float* h   = nullptr; cudaGetSymbolAddress((void**)&h,   g_h);
    float* agg = nullptr; cudaGetSymbolAddress((void**)&agg, g_agg);

    const int nthr = 256;
    k_zero  <<<(N_NODES + nthr - 1) / nthr, nthr>>>();
    k_count <<<(N_EDGES + nthr - 1) / nthr, nthr>>>(dst);
    k_scan1 <<<N_SCAN_BLKS, SCAN_BLK>>>();
    k_scan2 <<<1, 64>>>();
    k_scan3 <<<N_SCAN_BLKS, SCAN_BLK>>>();
    k_gstart<<<1, N_GRAPHS + 1>>>(batch);
    k_fill  <<<(N_EDGES + nthr - 1) / nthr, nthr>>>(src, dst);

    const int gemm_grid = (N_NODES + 127) / 128;
    const int agg_grid  = (N_NODES + 7) / 8;

    k_gemm_tc<<<gemm_grid, 256>>>(x, W1, h);
    k_agg    <<<agg_grid, 256>>>(h, b1, agg, 1);
    k_gemm_tc<<<gemm_grid, 256>>>(agg, W2, h);
    k_agg    <<<agg_grid, 256>>>(h, b2, agg, 1);
    k_gemm_tc<<<gemm_grid, 256>>>(agg, W3, h);
    k_agg    <<<agg_grid, 256>>>(h, b3, agg, 0);

    k_pool1<<<dim3(N_GRAPHS, POOL_CHUNKS), D>>>();
    k_pool2<<<N_GRAPHS, D>>>(out);
}

// round 5
// speedup vs baseline: 1.6637x; 1.0705x over previous
#include <cuda_runtime.h>
#include <cuda_bf16.h>
#include <math_constants.h>
#include <cstdint>

#define N_NODES 50000
#define N_EDGES 800000
#define D 128
#define N_GRAPHS 64
#define SCAN_BLK 1024
#define N_SCAN_BLKS ((N_NODES + SCAN_BLK - 1) / SCAN_BLK)   // 49
#define POOL_CHUNKS 8

// ------------------------- device scratch ----------------------------------
__device__ float g_dis[N_NODES];
__device__ int   g_deg[N_NODES];            // zeroed by k_scan23 for next call
__device__ int   g_rowoff[N_NODES + 1];
__device__ int   g_next[N_NODES];
__device__ int   g_bsum[N_SCAN_BLKS];
__device__ int   g_col[N_EDGES];
__device__ float g_h[N_NODES * D];          // dis-scaled x @ W
__device__ float g_agg[N_NODES * D];
__device__ float g_pmax[N_GRAPHS * POOL_CHUNKS * D];

// ------------------------- CSR build ---------------------------------------
__global__ void k_count(const int* __restrict__ dst) {
    int i = blockIdx.x * blockDim.x + threadIdx.x;
    if (i < N_EDGES) atomicAdd(&g_deg[dst[i]], 1);
}

// warp-shuffle block scan: local exclusive offsets + block sums + deg_inv_sqrt
__global__ __launch_bounds__(SCAN_BLK) void k_scan1() {
    __shared__ int wsum[32];
    int t = threadIdx.x;
    int lane = t & 31, warp = t >> 5;
    int i = blockIdx.x * SCAN_BLK + t;
    int v = (i < N_NODES) ? g_deg[i] : 0;
    // warp inclusive scan
    int incl = v;
#pragma unroll
    for (int off = 1; off < 32; off <<= 1) {
        int u = __shfl_up_sync(0xffffffffu, incl, off);
        if (lane >= off) incl += u;
    }
    if (lane == 31) wsum[warp] = incl;
    __syncthreads();
    if (warp == 0) {
        int w = wsum[lane];
        int wi = w;
#pragma unroll
        for (int off = 1; off < 32; off <<= 1) {
            int u = __shfl_up_sync(0xffffffffu, wi, off);
            if (lane >= off) wi += u;
        }
        wsum[lane] = wi - w;    // exclusive warp offsets
    }
    __syncthreads();
    int inclTot = incl + wsum[warp];
    if (i < N_NODES) {
        g_rowoff[i] = inclTot - v;              // exclusive within block
        g_dis[i] = rsqrtf((float)v + 1.0f);
    }
    if (t == SCAN_BLK - 1) g_bsum[blockIdx.x] = inclTot;
}

// each block: redundantly scan 49 block sums, apply offset, init g_next,
// and zero g_deg for the next invocation (count has already consumed it).
__global__ __launch_bounds__(SCAN_BLK) void k_scan23() {
    __shared__ int s[64];
    int t = threadIdx.x;
    if (t < 64) {
        int v = (t < N_SCAN_BLKS) ? g_bsum[t] : 0;
        s[t] = v;
        __syncthreads();
#pragma unroll
        for (int off = 1; off < 64; off <<= 1) {
            int add = (t >= off) ? s[t - off] : 0;
            __syncthreads();
            s[t] += add;
            __syncthreads();
        }
        int v2 = (t < N_SCAN_BLKS) ? g_bsum[t] : 0;
        s[t] -= v2;                 // exclusive
    } else {
        // must participate in the same barriers
        __syncthreads();
#pragma unroll
        for (int off = 1; off < 64; off <<= 1) { __syncthreads(); __syncthreads(); }
    }
    __syncthreads();
    int boff = s[blockIdx.x];
    int i = blockIdx.x * SCAN_BLK + t;
    if (i < N_NODES) {
        int fin = g_rowoff[i] + boff;
        g_rowoff[i] = fin;
        g_next[i] = fin;
        g_deg[i] = 0;               // ready for next invocation's k_count
    }
    if (i == 0) g_rowoff[N_NODES] = N_EDGES;
}

__global__ void k_fill(const int* __restrict__ src, const int* __restrict__ dst) {
    int i = blockIdx.x * blockDim.x + threadIdx.x;
    if (i < N_EDGES) {
        int pos = atomicAdd(&g_next[dst[i]], 1);
        g_col[pos] = src[i];
    }
}

// ------------------------- tensor-core GEMM (3xTF32), dis-scaled epilogue --
__device__ __forceinline__ void split_tf32(float x, float& hi, float& lo) {
    uint32_t u;
    asm("cvt.rna.tf32.f32 %0, %1;" : "=r"(u) : "f"(x));
    hi = __uint_as_float(u);
    float r = x - hi;
    asm("cvt.rna.tf32.f32 %0, %1;" : "=r"(u) : "f"(r));
    lo = __uint_as_float(u);
}

#define MMA_TF32(C, A0, A1, A2, A3, B0, B1)                                   \
    asm volatile(                                                             \
        "mma.sync.aligned.m16n8k8.row.col.f32.tf32.tf32.f32 "                 \
        "{%0,%1,%2,%3}, {%4,%5,%6,%7}, {%8,%9}, {%0,%1,%2,%3};"               \
        : "+f"(C[0]), "+f"(C[1]), "+f"(C[2]), "+f"(C[3])                      \
        : "r"(A0), "r"(A1), "r"(A2), "r"(A3), "r"(B0), "r"(B1))

__global__ __launch_bounds__(256) void k_gemm_tc(const float* __restrict__ A,
                                                 const float* __restrict__ Wm,
                                                 float* __restrict__ Hout) {
    __shared__ float Ah[128][20], Al[128][20];
    __shared__ float Wh[16][132], Wl[16][132];
    int tid  = threadIdx.x;
    int warp = tid >> 5, lane = tid & 31;
    int g = lane >> 2, tg = lane & 3;
    int row0 = blockIdx.x * 128;
    int wrow = warp * 16;

    float acc[16][4];
#pragma unroll
    for (int n = 0; n < 16; n++)
#pragma unroll
        for (int c = 0; c < 4; c++) acc[n][c] = 0.0f;

    for (int kc = 0; kc < 128; kc += 16) {
#pragma unroll
        for (int i = tid; i < 512; i += 256) {
            int r  = i >> 5;
            int c4 = (i & 31) * 4;
            float4 v = *(const float4*)(Wm + (size_t)(kc + r) * 128 + c4);
            float4 h4, l4;
            split_tf32(v.x, h4.x, l4.x); split_tf32(v.y, h4.y, l4.y);
            split_tf32(v.z, h4.z, l4.z); split_tf32(v.w, h4.w, l4.w);
            *(float4*)&Wh[r][c4] = h4;
            *(float4*)&Wl[r][c4] = l4;
        }
#pragma unroll
        for (int i = tid; i < 512; i += 256) {
            int r  = i >> 2;
            int c4 = (i & 3) * 4;
            int gr = row0 + r;
            float4 v = make_float4(0.f, 0.f, 0.f, 0.f);
            if (gr < N_NODES)
                v = *(const float4*)(A + (size_t)gr * 128 + kc + c4);
            float4 h4, l4;
            split_tf32(v.x, h4.x, l4.x); split_tf32(v.y, h4.y, l4.y);
            split_tf32(v.z, h4.z, l4.z); split_tf32(v.w, h4.w, l4.w);
            *(float4*)&Ah[r][c4] = h4;
            *(float4*)&Al[r][c4] = l4;
        }
        __syncthreads();

#pragma unroll
        for (int ks = 0; ks < 16; ks += 8) {
            uint32_t ah0 = __float_as_uint(Ah[wrow + g    ][ks + tg    ]);
            uint32_t ah1 = __float_as_uint(Ah[wrow + g + 8][ks + tg    ]);
            uint32_t ah2 = __float_as_uint(Ah[wrow + g    ][ks + tg + 4]);
            uint32_t ah3 = __float_as_uint(Ah[wrow + g + 8][ks + tg + 4]);
            uint32_t al0 = __float_as_uint(Al[wrow + g    ][ks + tg    ]);
            uint32_t al1 = __float_as_uint(Al[wrow + g + 8][ks + tg    ]);
            uint32_t al2 = __float_as_uint(Al[wrow + g    ][ks + tg + 4]);
            uint32_t al3 = __float_as_uint(Al[wrow + g + 8][ks + tg + 4]);
#pragma unroll
            for (int nt = 0; nt < 16; nt++) {
                int n0 = nt * 8;
                uint32_t bh0 = __float_as_uint(Wh[ks + tg    ][n0 + g]);
                uint32_t bh1 = __float_as_uint(Wh[ks + tg + 4][n0 + g]);
                uint32_t bl0 = __float_as_uint(Wl[ks + tg    ][n0 + g]);
                uint32_t bl1 = __float_as_uint(Wl[ks + tg + 4][n0 + g]);
                MMA_TF32(acc[nt], ah0, ah1, ah2, ah3, bh0, bh1);
                MMA_TF32(acc[nt], ah0, ah1, ah2, ah3, bl0, bl1);
                MMA_TF32(acc[nt], al0, al1, al2, al3, bh0, bh1);
            }
        }
        __syncthreads();
    }

    // epilogue: scale row r by dis[r], store
    int r0 = row0 + wrow + g;
    int r1 = r0 + 8;
    float s0 = (r0 < N_NODES) ? g_dis[r0] : 0.f;
    float s1 = (r1 < N_NODES) ? g_dis[r1] : 0.f;
#pragma unroll
    for (int nt = 0; nt < 16; nt++) {
        int c0 = nt * 8 + tg * 2;
        if (r0 < N_NODES)
            *(float2*)(Hout + (size_t)r0 * 128 + c0) =
                make_float2(acc[nt][0] * s0, acc[nt][1] * s0);
        if (r1 < N_NODES)
            *(float2*)(Hout + (size_t)r1 * 128 + c0) =
                make_float2(acc[nt][2] * s1, acc[nt][3] * s1);
    }
}

// ------------------------- aggregation: one warp per node ------------------
// hs is dis-scaled. out_i = dis_i * (sum_e hs[col_e] + hs_i) + b
__global__ __launch_bounds__(256) void k_agg(const float* __restrict__ hs,
                                             const float* __restrict__ b,
                                             float* __restrict__ out,
                                             int do_relu) {
    int lane = threadIdx.x & 31;
    int node = blockIdx.x * (blockDim.x >> 5) + (threadIdx.x >> 5);
    if (node >= N_NODES) return;
    int beg = g_rowoff[node], end = g_rowoff[node + 1];
    const float4* __restrict__ h4 = (const float4*)hs;
    float4 acc = h4[(size_t)node * 32 + lane];      // self-loop term
    for (int e0 = beg; e0 < end; e0 += 32) {
        int n = min(32, end - e0);
        int c = (lane < n) ? g_col[e0 + lane] : 0;
        for (int j = 0; j < n; j++) {
            int cj = __shfl_sync(0xffffffffu, c, j);
            float4 hv = h4[(size_t)cj * 32 + lane];
            acc.x += hv.x; acc.y += hv.y;
            acc.z += hv.z; acc.w += hv.w;
        }
    }
    float dis = g_dis[node];
    float4 bv = ((const float4*)b)[lane];
    acc.x = acc.x * dis + bv.x; acc.y = acc.y * dis + bv.y;
    acc.z = acc.z * dis + bv.z; acc.w = acc.w * dis + bv.w;
    if (do_relu) {
        acc.x = fmaxf(acc.x, 0.f); acc.y = fmaxf(acc.y, 0.f);
        acc.z = fmaxf(acc.z, 0.f); acc.w = fmaxf(acc.w, 0.f);
    }
    ((float4*)out)[(size_t)node * 32 + lane] = acc;
}

// ------------------------- pooling (graph bounds via binary search) --------
__device__ __forceinline__ int lower_bound_batch(const int* __restrict__ batch, int g) {
    int lo = 0, hi = N_NODES;
    while (lo < hi) {
        int mid = (lo + hi) >> 1;
        if (batch[mid] < g) lo = mid + 1; else hi = mid;
    }
    return lo;
}

__global__ void k_pool1(const int* __restrict__ batch) {
    int g = blockIdx.x, c = blockIdx.y, t = threadIdx.x;
    int beg = lower_bound_batch(batch, g);
    int end = lower_bound_batch(batch, g + 1);
    int len = end - beg;
    int chunk = (len + POOL_CHUNKS - 1) / POOL_CHUNKS;
    int s = beg + c * chunk;
    int e = min(end, s + chunk);
    float m = -CUDART_INF_F;
    for (int r = s; r < e; r++)
        m = fmaxf(m, g_agg[(size_t)r * D + t]);
    g_pmax[(size_t)(g * POOL_CHUNKS + c) * D + t] = m;
}

__global__ void k_pool2(float* __restrict__ out) {
    int g = blockIdx.x, t = threadIdx.x;
    float m = -CUDART_INF_F;
#pragma unroll
    for (int c = 0; c < POOL_CHUNKS; c++)
        m = fmaxf(m, g_pmax[(size_t)(g * POOL_CHUNKS + c) * D + t]);
    out[(size_t)g * D + t] = m;
}

// ------------------------- launch ------------------------------------------
extern "C" void kernel_launch(void* const* d_in, const int* in_sizes, int n_in,
                              void* d_out, int out_size) {
    const float* x  = (const float*)d_in[0];
    const float* W1 = (const float*)d_in[1];
    const float* b1 = (const float*)d_in[2];
    const float* W2 = (const float*)d_in[3];
    const float* b2 = (const float*)d_in[4];
    const float* W3 = (const float*)d_in[5];
    const float* b3 = (const float*)d_in[6];
    const int* edge_index = (const int*)d_in[7];
    const int* batch = (const int*)d_in[8];
    const int* src = edge_index;
    const int* dst = edge_index + N_EDGES;
    float* out = (float*)d_out;

    float* h   = nullptr; cudaGetSymbolAddress((void**)&h,   g_h);
    float* agg = nullptr; cudaGetSymbolAddress((void**)&agg, g_agg);

    const int nthr = 256;
    const int gemm_grid = (N_NODES + 127) / 128;
    const int agg_grid  = (N_NODES + 7) / 8;

    // NOTE: g_deg must be zero on entry — guaranteed by BSS init on first call
    // and by k_scan23 zeroing it on every call thereafter.
    k_count <<<(N_EDGES + nthr - 1) / nthr, nthr>>>(dst);       // 1
    k_scan1 <<<N_SCAN_BLKS, SCAN_BLK>>>();                       // 2
    k_scan23<<<N_SCAN_BLKS, SCAN_BLK>>>();                       // 3
    k_gemm_tc<<<gemm_grid, 256>>>(x, W1, h);                     // 4 (profiled)
    k_fill  <<<(N_EDGES + nthr - 1) / nthr, nthr>>>(src, dst);   // 5

    k_agg    <<<agg_grid, 256>>>(h, b1, agg, 1);                 // 6
    k_gemm_tc<<<gemm_grid, 256>>>(agg, W2, h);
    k_agg    <<<agg_grid, 256>>>(h, b2, agg, 1);
    k_gemm_tc<<<gemm_grid, 256>>>(agg, W3, h);
    k_agg    <<<agg_grid, 256>>>(h, b3, agg, 0);

    k_pool1<<<dim3(N_GRAPHS, POOL_CHUNKS), D>>>(batch);
    k_pool2<<<N_GRAPHS, D>>>(out);
}

// round 8
// speedup vs baseline: 1.8335x; 1.1021x over previous
#include <cuda_runtime.h>
#include <cuda_bf16.h>
#include <math_constants.h>
#include <cstdint>

#define N_NODES 50000
#define N_EDGES 800000
#define D 128
#define N_GRAPHS 64
#define SCAN_BLK 1024
#define N_SCAN_BLKS ((N_NODES + SCAN_BLK - 1) / SCAN_BLK)   // 49
#define POOL_CHUNKS 8

// GEMM smem layout (floats): W stride 136 (16B-aligned rows, conflict-free),
// A stride 20. Two buffers each for Wh/Wl/Ah/Al.
#define WSTR 136
#define ASTR 20
#define WBUF (16 * WSTR)      // 2176
#define ABUF (128 * ASTR)     // 2560
#define SM_WH 0
#define SM_WL (2 * WBUF)                  // 4352
#define SM_AH (4 * WBUF)                  // 8704
#define SM_AL (4 * WBUF + 2 * ABUF)       // 13824
#define SM_FLOATS (4 * WBUF + 4 * ABUF)   // 18944
#define SM_BYTES (SM_FLOATS * 4)          // 75776

// ------------------------- device scratch ----------------------------------
__device__ float g_dis[N_NODES];
__device__ int   g_deg[N_NODES];            // zeroed by k_scan23 for next call
__device__ int   g_rowoff[N_NODES + 1];
__device__ int   g_next[N_NODES];
__device__ int   g_bsum[N_SCAN_BLKS];
__device__ int   g_col[N_EDGES];
__device__ float g_h[N_NODES * D];          // dis-scaled x @ W
__device__ float g_agg[N_NODES * D];
__device__ float g_pmax[N_GRAPHS * POOL_CHUNKS * D];
__device__ float g_Wh[3 * D * D];           // pre-split weights (tf32 hi)
__device__ float g_Wl[3 * D * D];           // pre-split weights (tf32 lo)

// ------------------------- helpers -----------------------------------------
__device__ __forceinline__ void split_tf32(float x, float& hi, float& lo) {
    uint32_t u;
    asm("cvt.rna.tf32.f32 %0, %1;" : "=r"(u) : "f"(x));
    hi = __uint_as_float(u);
    float r = x - hi;
    asm("cvt.rna.tf32.f32 %0, %1;" : "=r"(u) : "f"(r));
    lo = __uint_as_float(u);
}

#define MMA_TF32(C, A0, A1, A2, A3, B0, B1)                                   \
    asm volatile(                                                             \
        "mma.sync.aligned.m16n8k8.row.col.f32.tf32.tf32.f32 "                 \
        "{%0,%1,%2,%3}, {%4,%5,%6,%7}, {%8,%9}, {%0,%1,%2,%3};"               \
        : "+f"(C[0]), "+f"(C[1]), "+f"(C[2]), "+f"(C[3])                      \
        : "r"(A0), "r"(A1), "r"(A2), "r"(A3), "r"(B0), "r"(B1))

__device__ __forceinline__ void cp_async16(float* dst_smem, const float* src) {
    unsigned d = (unsigned)__cvta_generic_to_shared(dst_smem);
    asm volatile("cp.async.cg.shared.global [%0], [%1], 16;" :: "r"(d), "l"(src));
}
__device__ __forceinline__ void cp_commit() {
    asm volatile("cp.async.commit_group;");
}
__device__ __forceinline__ void cp_wait0() {
    asm volatile("cp.async.wait_group 0;");
}

// ------------------------- CSR build ---------------------------------------
__global__ void k_count(const int* __restrict__ dst) {
    int i = blockIdx.x * blockDim.x + threadIdx.x;
    if (i < N_EDGES) atomicAdd(&g_deg[dst[i]], 1);
}

__global__ __launch_bounds__(SCAN_BLK) void k_scan1() {
    __shared__ int wsum[32];
    int t = threadIdx.x;
    int lane = t & 31, warp = t >> 5;
    int i = blockIdx.x * SCAN_BLK + t;
    int v = (i < N_NODES) ? g_deg[i] : 0;
    int incl = v;
#pragma unroll
    for (int off = 1; off < 32; off <<= 1) {
        int u = __shfl_up_sync(0xffffffffu, incl, off);
        if (lane >= off) incl += u;
    }
    if (lane == 31) wsum[warp] = incl;
    __syncthreads();
    if (warp == 0) {
        int w = wsum[lane];
        int wi = w;
#pragma unroll
        for (int off = 1; off < 32; off <<= 1) {
            int u = __shfl_up_sync(0xffffffffu, wi, off);
            if (lane >= off) wi += u;
        }
        wsum[lane] = wi - w;
    }
    __syncthreads();
    int inclTot = incl + wsum[warp];
    if (i < N_NODES) {
        g_rowoff[i] = inclTot - v;
        g_dis[i] = rsqrtf((float)v + 1.0f);
    }
    if (t == SCAN_BLK - 1) g_bsum[blockIdx.x] = inclTot;
}

__global__ __launch_bounds__(SCAN_BLK) void k_scan23() {
    __shared__ int s[64];
    int t = threadIdx.x;
    if (t < 64) {
        int v = (t < N_SCAN_BLKS) ? g_bsum[t] : 0;
        s[t] = v;
        __syncthreads();
#pragma unroll
        for (int off = 1; off < 64; off <<= 1) {
            int add = (t >= off) ? s[t - off] : 0;
            __syncthreads();
            s[t] += add;
            __syncthreads();
        }
        int v2 = (t < N_SCAN_BLKS) ? g_bsum[t] : 0;
        s[t] -= v2;
    } else {
        __syncthreads();
#pragma unroll
        for (int off = 1; off < 64; off <<= 1) { __syncthreads(); __syncthreads(); }
    }
    __syncthreads();
    int boff = s[blockIdx.x];
    int i = blockIdx.x * SCAN_BLK + t;
    if (i < N_NODES) {
        int fin = g_rowoff[i] + boff;
        g_rowoff[i] = fin;
        g_next[i] = fin;
        g_deg[i] = 0;
    }
    if (i == 0) g_rowoff[N_NODES] = N_EDGES;
}

__global__ void k_fill(const int* __restrict__ src, const int* __restrict__ dst) {
    int i = blockIdx.x * blockDim.x + threadIdx.x;
    if (i < N_EDGES) {
        int pos = atomicAdd(&g_next[dst[i]], 1);
        g_col[pos] = src[i];
    }
}

// ------------------------- weight pre-split --------------------------------
__global__ void k_splitW(const float* __restrict__ W1,
                         const float* __restrict__ W2,
                         const float* __restrict__ W3) {
    int i = blockIdx.x * blockDim.x + threadIdx.x;     // 0..49151
    if (i >= 3 * D * D) return;
    int m = i >> 14, j = i & (D * D - 1);
    const float* Ws = (m == 0) ? W1 : ((m == 1) ? W2 : W3);
    float hi, lo;
    split_tf32(Ws[j], hi, lo);
    g_Wh[i] = hi;
    g_Wl[i] = lo;
}

// ------------------------- pipelined tensor-core GEMM (3xTF32) -------------
// 256 threads, M-tile 128, N=128, K chunk 16, double-buffered (cp.async W,
// register-staged A). Epilogue scales row i by dis[i].
__global__ __launch_bounds__(256, 2) void k_gemm_tc(const float* __restrict__ A,
                                                    const float* __restrict__ Whg,
                                                    const float* __restrict__ Wlg,
                                                    float* __restrict__ Hout) {
    extern __shared__ float sm[];
    int tid  = threadIdx.x;
    int warp = tid >> 5, lane = tid & 31;
    int g = lane >> 2, tg = lane & 3;
    int row0 = blockIdx.x * 128;
    int wrow = warp * 16;

    // per-thread copy coordinates
    int wr0 = tid >> 5,  wc0 = (tid & 31) * 4;          // W: i = tid
    int wr1 = (tid + 256) >> 5, wc1 = wc0;              // W: i = tid+256
    int ar0 = tid >> 2,  ac0 = (tid & 3) * 4;           // A: i = tid
    int ar1 = (tid + 256) >> 2, ac1 = ac0;              // A: i = tid+256
    int gr0 = row0 + ar0, gr1 = row0 + ar1;

    float acc[16][4];
#pragma unroll
    for (int n = 0; n < 16; n++)
#pragma unroll
        for (int c = 0; c < 4; c++) acc[n][c] = 0.0f;

    // ---- prologue: stage chunk 0 into buffer 0
    cp_async16(sm + SM_WH + wr0 * WSTR + wc0, Whg + wr0 * D + wc0);
    cp_async16(sm + SM_WH + wr1 * WSTR + wc1, Whg + wr1 * D + wc1);
    cp_async16(sm + SM_WL + wr0 * WSTR + wc0, Wlg + wr0 * D + wc0);
    cp_async16(sm + SM_WL + wr1 * WSTR + wc1, Wlg + wr1 * D + wc1);
    cp_commit();
    {
        float4 a0 = make_float4(0.f, 0.f, 0.f, 0.f), a1 = a0;
        if (gr0 < N_NODES) a0 = *(const float4*)(A + (size_t)gr0 * D + ac0);
        if (gr1 < N_NODES) a1 = *(const float4*)(A + (size_t)gr1 * D + ac1);
        float4 h4, l4;
        split_tf32(a0.x, h4.x, l4.x); split_tf32(a0.y, h4.y, l4.y);
        split_tf32(a0.z, h4.z, l4.z); split_tf32(a0.w, h4.w, l4.w);
        *(float4*)(sm + SM_AH + ar0 * ASTR + ac0) = h4;
        *(float4*)(sm + SM_AL + ar0 * ASTR + ac0) = l4;
        split_tf32(a1.x, h4.x, l4.x); split_tf32(a1.y, h4.y, l4.y);
        split_tf32(a1.z, h4.z, l4.z); split_tf32(a1.w, h4.w, l4.w);
        *(float4*)(sm + SM_AH + ar1 * ASTR + ac1) = h4;
        *(float4*)(sm + SM_AL + ar1 * ASTR + ac1) = l4;
    }
    cp_wait0();
    __syncthreads();

    for (int kc = 0; kc < 8; kc++) {
        int buf = kc & 1, nxt = buf ^ 1;
        float4 a0, a1;
        bool pre = (kc < 7);
        if (pre) {
            // prefetch W chunk kc+1 (async) and A chunk kc+1 (regs)
            const float* wh = Whg + (kc + 1) * 16 * D;
            const float* wl = Wlg + (kc + 1) * 16 * D;
            cp_async16(sm + SM_WH + nxt * WBUF + wr0 * WSTR + wc0, wh + wr0 * D + wc0);
            cp_async16(sm + SM_WH + nxt * WBUF + wr1 * WSTR + wc1, wh + wr1 * D + wc1);
            cp_async16(sm + SM_WL + nxt * WBUF + wr0 * WSTR + wc0, wl + wr0 * D + wc0);
            cp_async16(sm + SM_WL + nxt * WBUF + wr1 * WSTR + wc1, wl + wr1 * D + wc1);
            cp_commit();
            int kcol = (kc + 1) * 16;
            a0 = make_float4(0.f, 0.f, 0.f, 0.f); a1 = a0;
            if (gr0 < N_NODES) a0 = *(const float4*)(A + (size_t)gr0 * D + kcol + ac0);
            if (gr1 < N_NODES) a1 = *(const float4*)(A + (size_t)gr1 * D + kcol + ac1);
        }

        // ---- MMAs on current buffer
        const float* AHs = sm + SM_AH + buf * ABUF;
        const float* ALs = sm + SM_AL + buf * ABUF;
        const float* WHs = sm + SM_WH + buf * WBUF;
        const float* WLs = sm + SM_WL + buf * WBUF;
#pragma unroll
        for (int ks = 0; ks < 16; ks += 8) {
            uint32_t ah0 = __float_as_uint(AHs[(wrow + g    ) * ASTR + ks + tg    ]);
            uint32_t ah1 = __float_as_uint(AHs[(wrow + g + 8) * ASTR + ks + tg    ]);
            uint32_t ah2 = __float_as_uint(AHs[(wrow + g    ) * ASTR + ks + tg + 4]);
            uint32_t ah3 = __float_as_uint(AHs[(wrow + g + 8) * ASTR + ks + tg + 4]);
            uint32_t al0 = __float_as_uint(ALs[(wrow + g    ) * ASTR + ks + tg    ]);
            uint32_t al1 = __float_as_uint(ALs[(wrow + g + 8) * ASTR + ks + tg    ]);
            uint32_t al2 = __float_as_uint(ALs[(wrow + g    ) * ASTR + ks + tg + 4]);
            uint32_t al3 = __float_as_uint(ALs[(wrow + g + 8) * ASTR + ks + tg + 4]);
#pragma unroll
            for (int nt = 0; nt < 16; nt++) {
                int n0 = nt * 8;
                uint32_t bh0 = __float_as_uint(WHs[(ks + tg    ) * WSTR + n0 + g]);
                uint32_t bh1 = __float_as_uint(WHs[(ks + tg + 4) * WSTR + n0 + g]);
                uint32_t bl0 = __float_as_uint(WLs[(ks + tg    ) * WSTR + n0 + g]);
                uint32_t bl1 = __float_as_uint(WLs[(ks + tg + 4) * WSTR + n0 + g]);
                MMA_TF32(acc[nt], ah0, ah1, ah2, ah3, bh0, bh1);
                MMA_TF32(acc[nt], ah0, ah1, ah2, ah3, bl0, bl1);
                MMA_TF32(acc[nt], al0, al1, al2, al3, bh0, bh1);
            }
        }

        if (pre) {
            float4 h4, l4;
            split_tf32(a0.x, h4.x, l4.x); split_tf32(a0.y, h4.y, l4.y);
            split_tf32(a0.z, h4.z, l4.z); split_tf32(a0.w, h4.w, l4.w);
            *(float4*)(sm + SM_AH + nxt * ABUF + ar0 * ASTR + ac0) = h4;
            *(float4*)(sm + SM_AL + nxt * ABUF + ar0 * ASTR + ac0) = l4;
            split_tf32(a1.x, h4.x, l4.x); split_tf32(a1.y, h4.y, l4.y);
            split_tf32(a1.z, h4.z, l4.z); split_tf32(a1.w, h4.w, l4.w);
            *(float4*)(sm + SM_AH + nxt * ABUF + ar1 * ASTR + ac1) = h4;
            *(float4*)(sm + SM_AL + nxt * ABUF + ar1 * ASTR + ac1) = l4;
            cp_wait0();
            __syncthreads();
        }
    }

    // ---- epilogue: scale row r by dis[r], store
    int r0 = row0 + wrow + g;
    int r1 = r0 + 8;
    float s0 = (r0 < N_NODES) ? g_dis[r0] : 0.f;
    float s1 = (r1 < N_NODES) ? g_dis[r1] : 0.f;
#pragma unroll
    for (int nt = 0; nt < 16; nt++) {
        int c0 = nt * 8 + tg * 2;
        if (r0 < N_NODES)
            *(float2*)(Hout + (size_t)r0 * D + c0) =
                make_float2(acc[nt][0] * s0, acc[nt][1] * s0);
        if (r1 < N_NODES)
            *(float2*)(Hout + (size_t)r1 * D + c0) =
                make_float2(acc[nt][2] * s1, acc[nt][3] * s1);
    }
}

// ------------------------- aggregation: one warp per node, MLP-8 gather ----
__global__ __launch_bounds__(256) void k_agg(const float* __restrict__ hs,
                                             const float* __restrict__ b,
                                             float* __restrict__ out,
                                             int do_relu) {
    int lane = threadIdx.x & 31;
    int node = blockIdx.x * (blockDim.x >> 5) + (threadIdx.x >> 5);
    if (node >= N_NODES) return;
    int beg = g_rowoff[node], end = g_rowoff[node + 1];
    const float4* __restrict__ h4 = (const float4*)hs;
    float4 acc = h4[(size_t)node * 32 + lane];      // self-loop term
    for (int e0 = beg; e0 < end; e0 += 32) {
        int n = min(32, end - e0);
        int c = (lane < n) ? g_col[e0 + lane] : 0;
        int j = 0;
        for (; j + 8 <= n; j += 8) {
            int cj[8];
#pragma unroll
            for (int u = 0; u < 8; u++) cj[u] = __shfl_sync(0xffffffffu, c, j + u);
            float4 hv[8];
#pragma unroll
            for (int u = 0; u < 8; u++) hv[u] = h4[(size_t)cj[u] * 32 + lane];
#pragma unroll
            for (int u = 0; u < 8; u++) {
                acc.x += hv[u].x; acc.y += hv[u].y;
                acc.z += hv[u].z; acc.w += hv[u].w;
            }
        }
        for (; j < n; j++) {
            int cj = __shfl_sync(0xffffffffu, c, j);
            float4 hv = h4[(size_t)cj * 32 + lane];
            acc.x += hv.x; acc.y += hv.y;
            acc.z += hv.z; acc.w += hv.w;
        }
    }
    float dis = g_dis[node];
    float4 bv = ((const float4*)b)[lane];
    acc.x = acc.x * dis + bv.x; acc.y = acc.y * dis + bv.y;
    acc.z = acc.z * dis + bv.z; acc.w = acc.w * dis + bv.w;
    if (do_relu) {
        acc.x = fmaxf(acc.x, 0.f); acc.y = fmaxf(acc.y, 0.f);
        acc.z = fmaxf(acc.z, 0.f); acc.w = fmaxf(acc.w, 0.f);
    }
    ((float4*)out)[(size_t)node * 32 + lane] = acc;
}

// ------------------------- pooling -----------------------------------------
__device__ __forceinline__ int lower_bound_batch(const int* __restrict__ batch, int g) {
    int lo = 0, hi = N_NODES;
    while (lo < hi) {
        int mid = (lo + hi) >> 1;
        if (batch[mid] < g) lo = mid + 1; else hi = mid;
    }
    return lo;
}

__global__ void k_pool1(const int* __restrict__ batch) {
    int g = blockIdx.x, c = blockIdx.y, t = threadIdx.x;
    int beg = lower_bound_batch(batch, g);
    int end = lower_bound_batch(batch, g + 1);
    int len = end - beg;
    int chunk = (len + POOL_CHUNKS - 1) / POOL_CHUNKS;
    int s = beg + c * chunk;
    int e = min(end, s + chunk);
    float m = -CUDART_INF_F;
    for (int r = s; r < e; r++)
        m = fmaxf(m, g_agg[(size_t)r * D + t]);
    g_pmax[(size_t)(g * POOL_CHUNKS + c) * D + t] = m;
}

__global__ void k_pool2(float* __restrict__ out) {
    int g = blockIdx.x, t = threadIdx.x;
    float m = -CUDART_INF_F;
#pragma unroll
    for (int c = 0; c < POOL_CHUNKS; c++)
        m = fmaxf(m, g_pmax[(size_t)(g * POOL_CHUNKS + c) * D + t]);
    out[(size_t)g * D + t] = m;
}

// ------------------------- launch ------------------------------------------
extern "C" void kernel_launch(void* const* d_in, const int* in_sizes, int n_in,
                              void* d_out, int out_size) {
    const float* x  = (const float*)d_in[0];
    const float* W1 = (const float*)d_in[1];
    const float* b1 = (const float*)d_in[2];
    const float* W2 = (const float*)d_in[3];
    const float* b2 = (const float*)d_in[4];
    const float* W3 = (const float*)d_in[5];
    const float* b3 = (const float*)d_in[6];
    const int* edge_index = (const int*)d_in[7];
    const int* batch = (const int*)d_in[8];
    const int* src = edge_index;
    const int* dst = edge_index + N_EDGES;
    float* out = (float*)d_out;

    float* h   = nullptr; cudaGetSymbolAddress((void**)&h,   g_h);
    float* agg = nullptr; cudaGetSymbolAddress((void**)&agg, g_agg);
    float* wh  = nullptr; cudaGetSymbolAddress((void**)&wh,  g_Wh);
    float* wl  = nullptr; cudaGetSymbolAddress((void**)&wl,  g_Wl);

    cudaFuncSetAttribute(k_gemm_tc, cudaFuncAttributeMaxDynamicSharedMemorySize,
                         SM_BYTES);

    const int nthr = 256;
    const int gemm_grid = (N_NODES + 127) / 128;
    const int agg_grid  = (N_NODES + 7) / 8;

    // g_deg zero on entry: BSS-init first call, k_scan23 re-zeroes each call.
    k_count <<<(N_EDGES + nthr - 1) / nthr, nthr>>>(dst);            // 1
    k_scan1 <<<N_SCAN_BLKS, SCAN_BLK>>>();                            // 2
    k_splitW<<<(3 * D * D + nthr - 1) / nthr, nthr>>>(W1, W2, W3);    // 3
    k_gemm_tc<<<gemm_grid, 256, SM_BYTES>>>(x, wh, wl, h);            // 4 (profiled)
    k_scan23<<<N_SCAN_BLKS, SCAN_BLK>>>();                            // 5
    k_fill  <<<(N_EDGES + nthr - 1) / nthr, nthr>>>(src, dst);        // 6

    k_agg    <<<agg_grid, 256>>>(h, b1, agg, 1);
    k_gemm_tc<<<gemm_grid, 256, SM_BYTES>>>(agg, wh + D * D, wl + D * D, h);
    k_agg    <<<agg_grid, 256>>>(h, b2, agg, 1);
    k_gemm_tc<<<gemm_grid, 256, SM_BYTES>>>(agg, wh + 2 * D * D, wl + 2 * D * D, h);
    k_agg    <<<agg_grid, 256>>>(h, b3, agg, 0);

    k_pool1<<<dim3(N_GRAPHS, POOL_CHUNKS), D>>>(batch);
    k_pool2<<<N_GRAPHS, D>>>(out);
}

// round 10
// speedup vs baseline: 2.2115x; 1.2062x over previous
#include <cuda_runtime.h>
#include <cuda_bf16.h>
#include <math_constants.h>
#include <cstdint>

#define N_NODES 50000
#define N_EDGES 800000
#define D 128
#define N_GRAPHS 64
#define SCAN_BLK 1024
#define N_SCAN_BLKS ((N_NODES + SCAN_BLK - 1) / SCAN_BLK)   // 49
#define POOL_CHUNKS 8

// GEMM smem layout in uint32 units (bf16x2 pairs).
// W tile: 8 k-pair rows x 128 n cols, stride 136 (==8 mod 32: conflict-free)
// A tile: 128 m rows x 8 k-pair cols, stride 12 (12g+tg hits all 32 banks)
#define WSTRB 136
#define WBUFB (8 * WSTRB)        // 1088
#define ASTRB 12
#define ABUFB (128 * ASTRB)      // 1536
#define S_WH 0
#define S_WL (2 * WBUFB)                   // 2176
#define S_AH (4 * WBUFB)                   // 4352
#define S_AL (4 * WBUFB + 2 * ABUFB)       // 7424
#define S_TOT (4 * WBUFB + 4 * ABUFB)      // 10496 u32 = 41984 B

// ------------------------- device scratch ----------------------------------
__device__ float    g_dis[N_NODES];
__device__ int      g_deg[N_NODES];         // zeroed by k_scan23 for next call
__device__ int      g_rowoff[N_NODES + 1];
__device__ int      g_next[N_NODES];
__device__ int      g_bsum[N_SCAN_BLKS];
__device__ int      g_col[N_EDGES];
__device__ float    g_h[N_NODES * D];       // dis-scaled x @ W
__device__ float    g_agg[N_NODES * D];
__device__ float    g_pmax[N_GRAPHS * POOL_CHUNKS * D];
__device__ uint32_t g_Wph[3 * 64 * 128];    // packed bf16x2 hi, [layer][kpair][n]
__device__ uint32_t g_Wpl[3 * 64 * 128];    // packed bf16x2 lo

// ------------------------- helpers -----------------------------------------
// split (x,y) into bf16 hi pair + bf16 lo pair, packed (low half = first elem)
__device__ __forceinline__ void split_pack(float x, float y,
                                           uint32_t& hi, uint32_t& lo) {
    __nv_bfloat162 h2 = __floats2bfloat162_rn(x, y);
    float rx = x - __bfloat162float(h2.x);
    float ry = y - __bfloat162float(h2.y);
    __nv_bfloat162 l2 = __floats2bfloat162_rn(rx, ry);
    hi = *reinterpret_cast<uint32_t*>(&h2);
    lo = *reinterpret_cast<uint32_t*>(&l2);
}

#define MMA_BF16(C, A0, A1, A2, A3, B0, B1)                                   \
    asm volatile(                                                             \
        "mma.sync.aligned.m16n8k16.row.col.f32.bf16.bf16.f32 "                \
        "{%0,%1,%2,%3}, {%4,%5,%6,%7}, {%8,%9}, {%0,%1,%2,%3};"               \
        : "+f"(C[0]), "+f"(C[1]), "+f"(C[2]), "+f"(C[3])                      \
        : "r"(A0), "r"(A1), "r"(A2), "r"(A3), "r"(B0), "r"(B1))

__device__ __forceinline__ void cp_async16u(uint32_t* dst_smem, const uint32_t* src) {
    unsigned d = (unsigned)__cvta_generic_to_shared(dst_smem);
    asm volatile("cp.async.cg.shared.global [%0], [%1], 16;" :: "r"(d), "l"(src));
}
__device__ __forceinline__ void cp_commit() {
    asm volatile("cp.async.commit_group;");
}
__device__ __forceinline__ void cp_wait0() {
    asm volatile("cp.async.wait_group 0;");
}

// ------------------------- CSR build ---------------------------------------
__global__ void k_count(const int* __restrict__ dst) {
    int i = blockIdx.x * blockDim.x + threadIdx.x;
    if (i < N_EDGES) atomicAdd(&g_deg[dst[i]], 1);
}

__global__ __launch_bounds__(SCAN_BLK) void k_scan1() {
    __shared__ int wsum[32];
    int t = threadIdx.x;
    int lane = t & 31, warp = t >> 5;
    int i = blockIdx.x * SCAN_BLK + t;
    int v = (i < N_NODES) ? g_deg[i] : 0;
    int incl = v;
#pragma unroll
    for (int off = 1; off < 32; off <<= 1) {
        int u = __shfl_up_sync(0xffffffffu, incl, off);
        if (lane >= off) incl += u;
    }
    if (lane == 31) wsum[warp] = incl;
    __syncthreads();
    if (warp == 0) {
        int w = wsum[lane];
        int wi = w;
#pragma unroll
        for (int off = 1; off < 32; off <<= 1) {
            int u = __shfl_up_sync(0xffffffffu, wi, off);
            if (lane >= off) wi += u;
        }
        wsum[lane] = wi - w;
    }
    __syncthreads();
    int inclTot = incl + wsum[warp];
    if (i < N_NODES) {
        g_rowoff[i] = inclTot - v;
        g_dis[i] = rsqrtf((float)v + 1.0f);
    }
    if (t == SCAN_BLK - 1) g_bsum[blockIdx.x] = inclTot;
}

__global__ __launch_bounds__(SCAN_BLK) void k_scan23() {
    __shared__ int s[64];
    int t = threadIdx.x;
    if (t < 64) {
        int v = (t < N_SCAN_BLKS) ? g_bsum[t] : 0;
        s[t] = v;
        __syncthreads();
#pragma unroll
        for (int off = 1; off < 64; off <<= 1) {
            int add = (t >= off) ? s[t - off] : 0;
            __syncthreads();
            s[t] += add;
            __syncthreads();
        }
        int v2 = (t < N_SCAN_BLKS) ? g_bsum[t] : 0;
        s[t] -= v2;
    } else {
        __syncthreads();
#pragma unroll
        for (int off = 1; off < 64; off <<= 1) { __syncthreads(); __syncthreads(); }
    }
    __syncthreads();
    int boff = s[blockIdx.x];
    int i = blockIdx.x * SCAN_BLK + t;
    if (i < N_NODES) {
        int fin = g_rowoff[i] + boff;
        g_rowoff[i] = fin;
        g_next[i] = fin;
        g_deg[i] = 0;
    }
    if (i == 0) g_rowoff[N_NODES] = N_EDGES;
}

__global__ void k_fill(const int* __restrict__ src, const int* __restrict__ dst) {
    int i = blockIdx.x * blockDim.x + threadIdx.x;
    if (i < N_EDGES) {
        int pos = atomicAdd(&g_next[dst[i]], 1);
        g_col[pos] = src[i];
    }
}

// ------------------------- weight pre-split (packed bf16 pairs) ------------
// g_Wp*[layer*8192 + kp*128 + n] = pack(bf16(W[2kp][n]), bf16(W[2kp+1][n]))
__global__ void k_splitW(const float* __restrict__ W1,
                         const float* __restrict__ W2,
                         const float* __restrict__ W3) {
    int i = blockIdx.x * blockDim.x + threadIdx.x;     // 0..24575
    if (i >= 3 * 64 * 128) return;
    int m = i >> 13, r = i & 8191;
    int kp = r >> 7, n = r & 127;
    const float* Ws = (m == 0) ? W1 : ((m == 1) ? W2 : W3);
    float x0 = Ws[(2 * kp) * D + n];
    float x1 = Ws[(2 * kp + 1) * D + n];
    uint32_t hi, lo;
    split_pack(x0, x1, hi, lo);
    g_Wph[i] = hi;
    g_Wpl[i] = lo;
}

// ------------------------- pipelined bf16x3 tensor-core GEMM ---------------
// 256 threads (8 warps as 4x2: M=32,N=64 per warp), M-tile 128, K chunk 16,
// double-buffered (cp.async W pairs, register-staged A split in-kernel).
// Epilogue scales row i by dis[i].
__global__ __launch_bounds__(256, 2) void k_gemm_tc(const float* __restrict__ A,
                                                    const uint32_t* __restrict__ Wph,
                                                    const uint32_t* __restrict__ Wpl,
                                                    float* __restrict__ Hout) {
    __shared__ uint32_t sm[S_TOT];
    int tid  = threadIdx.x;
    int warp = tid >> 5, lane = tid & 31;
    int g = lane >> 2, tg = lane & 3;
    int wm = warp & 3, wn = warp >> 2;          // 4x2 warp grid
    int row0 = blockIdx.x * 128;

    // copy coordinates
    int wr = tid >> 5, wc = lane * 4;           // W chunk: 8 rows x 128 u32
    int ar = tid >> 2;                          // A rows ar and ar+64
    int afc = (tid & 3) * 4;                    // float col in k16 chunk
    int apc = (tid & 3) * 2;                    // pair col

    float acc[2][8][4];
#pragma unroll
    for (int mt = 0; mt < 2; mt++)
#pragma unroll
        for (int nt = 0; nt < 8; nt++)
#pragma unroll
            for (int c = 0; c < 4; c++) acc[mt][nt][c] = 0.0f;

    // ---- prologue: stage chunk 0 into buffer 0
    cp_async16u(&sm[S_WH + wr * WSTRB + wc], Wph + wr * 128 + wc);
    cp_async16u(&sm[S_WL + wr * WSTRB + wc], Wpl + wr * 128 + wc);
    cp_commit();
#pragma unroll
    for (int p = 0; p < 2; p++) {
        int rr = ar + p * 64;
        int gr = row0 + rr;
        float4 v = make_float4(0.f, 0.f, 0.f, 0.f);
        if (gr < N_NODES) v = *(const float4*)(A + (size_t)gr * D + afc);
        uint32_t h0, l0, h1, l1;
        split_pack(v.x, v.y, h0, l0);
        split_pack(v.z, v.w, h1, l1);
        sm[S_AH + rr * ASTRB + apc]     = h0;
        sm[S_AH + rr * ASTRB + apc + 1] = h1;
        sm[S_AL + rr * ASTRB + apc]     = l0;
        sm[S_AL + rr * ASTRB + apc + 1] = l1;
    }
    cp_wait0();
    __syncthreads();

    for (int kc = 0; kc < 8; kc++) {
        int buf = kc & 1, nxt = buf ^ 1;
        bool pre = (kc < 7);
        float4 v0, v1;
        if (pre) {
            const uint32_t* wh = Wph + (kc + 1) * 1024;
            const uint32_t* wl = Wpl + (kc + 1) * 1024;
            cp_async16u(&sm[S_WH + nxt * WBUFB + wr * WSTRB + wc], wh + wr * 128 + wc);
            cp_async16u(&sm[S_WL + nxt * WBUFB + wr * WSTRB + wc], wl + wr * 128 + wc);
            cp_commit();
            int kcol = (kc + 1) * 16 + afc;
            v0 = make_float4(0.f, 0.f, 0.f, 0.f); v1 = v0;
            int gr0 = row0 + ar, gr1 = gr0 + 64;
            if (gr0 < N_NODES) v0 = *(const float4*)(A + (size_t)gr0 * D + kcol);
            if (gr1 < N_NODES) v1 = *(const float4*)(A + (size_t)gr1 * D + kcol);
        }

        // ---- MMAs on current buffer (one k16 step)
        const uint32_t* AH = sm + S_AH + buf * ABUFB;
        const uint32_t* AL = sm + S_AL + buf * ABUFB;
        const uint32_t* WH = sm + S_WH + buf * WBUFB;
        const uint32_t* WL = sm + S_WL + buf * WBUFB;

        uint32_t ah[2][4], al[2][4];
#pragma unroll
        for (int mt = 0; mt < 2; mt++) {
            int rb  = (wm * 32 + mt * 16 + g) * ASTRB;
            int rb8 = rb + 8 * ASTRB;
            ah[mt][0] = AH[rb + tg];       ah[mt][1] = AH[rb8 + tg];
            ah[mt][2] = AH[rb + tg + 4];   ah[mt][3] = AH[rb8 + tg + 4];
            al[mt][0] = AL[rb + tg];       al[mt][1] = AL[rb8 + tg];
            al[mt][2] = AL[rb + tg + 4];   al[mt][3] = AL[rb8 + tg + 4];
        }
#pragma unroll
        for (int nt = 0; nt < 8; nt++) {
            int nc = wn * 64 + nt * 8 + g;
            uint32_t bh0 = WH[tg * WSTRB + nc];
            uint32_t bh1 = WH[(tg + 4) * WSTRB + nc];
            uint32_t bl0 = WL[tg * WSTRB + nc];
            uint32_t bl1 = WL[(tg + 4) * WSTRB + nc];
#pragma unroll
            for (int mt = 0; mt < 2; mt++) {
                MMA_BF16(acc[mt][nt], ah[mt][0], ah[mt][1], ah[mt][2], ah[mt][3], bh0, bh1);
                MMA_BF16(acc[mt][nt], ah[mt][0], ah[mt][1], ah[mt][2], ah[mt][3], bl0, bl1);
                MMA_BF16(acc[mt][nt], al[mt][0], al[mt][1], al[mt][2], al[mt][3], bh0, bh1);
            }
        }

        if (pre) {
            uint32_t h0, l0, h1, l1;
            split_pack(v0.x, v0.y, h0, l0);
            split_pack(v0.z, v0.w, h1, l1);
            sm[S_AH + nxt * ABUFB + ar * ASTRB + apc]     = h0;
            sm[S_AH + nxt * ABUFB + ar * ASTRB + apc + 1] = h1;
            sm[S_AL + nxt * ABUFB + ar * ASTRB + apc]     = l0;
            sm[S_AL + nxt * ABUFB + ar * ASTRB + apc + 1] = l1;
            split_pack(v1.x, v1.y, h0, l0);
            split_pack(v1.z, v1.w, h1, l1);
            sm[S_AH + nxt * ABUFB + (ar + 64) * ASTRB + apc]     = h0;
            sm[S_AH + nxt * ABUFB + (ar + 64) * ASTRB + apc + 1] = h1;
            sm[S_AL + nxt * ABUFB + (ar + 64) * ASTRB + apc]     = l0;
            sm[S_AL + nxt * ABUFB + (ar + 64) * ASTRB + apc + 1] = l1;
            cp_wait0();
            __syncthreads();
        }
    }

    // ---- epilogue: scale row r by dis[r], store
#pragma unroll
    for (int mt = 0; mt < 2; mt++) {
        int r0 = row0 + wm * 32 + mt * 16 + g;
        int r1 = r0 + 8;
        float s0 = (r0 < N_NODES) ? g_dis[r0] : 0.f;
        float s1 = (r1 < N_NODES) ? g_dis[r1] : 0.f;
#pragma unroll
        for (int nt = 0; nt < 8; nt++) {
            int c0 = wn * 64 + nt * 8 + tg * 2;
            if (r0 < N_NODES)
                *(float2*)(Hout + (size_t)r0 * D + c0) =
                    make_float2(acc[mt][nt][0] * s0, acc[mt][nt][1] * s0);
            if (r1 < N_NODES)
                *(float2*)(Hout + (size_t)r1 * D + c0) =
                    make_float2(acc[mt][nt][2] * s1, acc[mt][nt][3] * s1);
        }
    }
}

// ------------------------- aggregation: one warp per node, MLP-8 gather ----
__global__ __launch_bounds__(256) void k_agg(const float* __restrict__ hs,
                                             const float* __restrict__ b,
                                             float* __restrict__ out,
                                             int do_relu) {
    int lane = threadIdx.x & 31;
    int node = blockIdx.x * (blockDim.x >> 5) + (threadIdx.x >> 5);
    if (node >= N_NODES) return;
    int beg = g_rowoff[node], end = g_rowoff[node + 1];
    const float4* __restrict__ h4 = (const float4*)hs;
    float4 acc = h4[(size_t)node * 32 + lane];      // self-loop term
    for (int e0 = beg; e0 < end; e0 += 32) {
        int n = min(32, end - e0);
        int c = (lane < n) ? g_col[e0 + lane] : 0;
        int j = 0;
        for (; j + 8 <= n; j += 8) {
            int cj[8];
#pragma unroll
            for (int u = 0; u < 8; u++) cj[u] = __shfl_sync(0xffffffffu, c, j + u);
            float4 hv[8];
#pragma unroll
            for (int u = 0; u < 8; u++) hv[u] = h4[(size_t)cj[u] * 32 + lane];
#pragma unroll
            for (int u = 0; u < 8; u++) {
                acc.x += hv[u].x; acc.y += hv[u].y;
                acc.z += hv[u].z; acc.w += hv[u].w;
            }
        }
        for (; j < n; j++) {
            int cj = __shfl_sync(0xffffffffu, c, j);
            float4 hv = h4[(size_t)cj * 32 + lane];
            acc.x += hv.x; acc.y += hv.y;
            acc.z += hv.z; acc.w += hv.w;
        }
    }
    float dis = g_dis[node];
    float4 bv = ((const float4*)b)[lane];
    acc.x = acc.x * dis + bv.x; acc.y = acc.y * dis + bv.y;
    acc.z = acc.z * dis + bv.z; acc.w = acc.w * dis + bv.w;
    if (do_relu) {
        acc.x = fmaxf(acc.x, 0.f); acc.y = fmaxf(acc.y, 0.f);
        acc.z = fmaxf(acc.z, 0.f); acc.w = fmaxf(acc.w, 0.f);
    }
    ((float4*)out)[(size_t)node * 32 + lane] = acc;
}

// ------------------------- pooling -----------------------------------------
__device__ __forceinline__ int lower_bound_batch(const int* __restrict__ batch, int g) {
    int lo = 0, hi = N_NODES;
    while (lo < hi) {
        int mid = (lo + hi) >> 1;
        if (batch[mid] < g) lo = mid + 1; else hi = mid;
    }
    return lo;
}

__global__ void k_pool1(const int* __restrict__ batch) {
    int g = blockIdx.x, c = blockIdx.y, t = threadIdx.x;
    int beg = lower_bound_batch(batch, g);
    int end = lower_bound_batch(batch, g + 1);
    int len = end - beg;
    int chunk = (len + POOL_CHUNKS - 1) / POOL_CHUNKS;
    int s = beg + c * chunk;
    int e = min(end, s + chunk);
    float m = -CUDART_INF_F;
    for (int r = s; r < e; r++)
        m = fmaxf(m, g_agg[(size_t)r * D + t]);
    g_pmax[(size_t)(g * POOL_CHUNKS + c) * D + t] = m;
}

__global__ void k_pool2(float* __restrict__ out) {
    int g = blockIdx.x, t = threadIdx.x;
    float m = -CUDART_INF_F;
#pragma unroll
    for (int c = 0; c < POOL_CHUNKS; c++)
        m = fmaxf(m, g_pmax[(size_t)(g * POOL_CHUNKS + c) * D + t]);
    out[(size_t)g * D + t] = m;
}

// ------------------------- launch ------------------------------------------
extern "C" void kernel_launch(void* const* d_in, const int* in_sizes, int n_in,
                              void* d_out, int out_size) {
    const float* x  = (const float*)d_in[0];
    const float* W1 = (const float*)d_in[1];
    const float* b1 = (const float*)d_in[2];
    const float* W2 = (const float*)d_in[3];
    const float* b2 = (const float*)d_in[4];
    const float* W3 = (const float*)d_in[5];
    const float* b3 = (const float*)d_in[6];
    const int* edge_index = (const int*)d_in[7];
    const int* batch = (const int*)d_in[8];
    const int* src = edge_index;
    const int* dst = edge_index + N_EDGES;
    float* out = (float*)d_out;

    float*    h   = nullptr; cudaGetSymbolAddress((void**)&h,   g_h);
    float*    agg = nullptr; cudaGetSymbolAddress((void**)&agg, g_agg);
    uint32_t* wh  = nullptr; cudaGetSymbolAddress((void**)&wh,  g_Wph);
    uint32_t* wl  = nullptr; cudaGetSymbolAddress((void**)&wl,  g_Wpl);

    const int nthr = 256;
    const int gemm_grid = (N_NODES + 127) / 128;
    const int agg_grid  = (N_NODES + 7) / 8;
    const int WSZ = 64 * 128;   // packed pairs per layer

    // g_deg zero on entry: BSS-init first call, k_scan23 re-zeroes each call.
    k_count <<<(N_EDGES + nthr - 1) / nthr, nthr>>>(dst);            // 1
    k_scan1 <<<N_SCAN_BLKS, SCAN_BLK>>>();                            // 2
    k_splitW<<<(3 * WSZ + nthr - 1) / nthr, nthr>>>(W1, W2, W3);      // 3
    k_gemm_tc<<<gemm_grid, 256>>>(x, wh, wl, h);                      // 4 (profiled)
    k_scan23<<<N_SCAN_BLKS, SCAN_BLK>>>();                            // 5
    k_fill  <<<(N_EDGES + nthr - 1) / nthr, nthr>>>(src, dst);        // 6

    k_agg    <<<agg_grid, 256>>>(h, b1, agg, 1);
    k_gemm_tc<<<gemm_grid, 256>>>(agg, wh + WSZ, wl + WSZ, h);
    k_agg    <<<agg_grid, 256>>>(h, b2, agg, 1);
    k_gemm_tc<<<gemm_grid, 256>>>(agg, wh + 2 * WSZ, wl + 2 * WSZ, h);
    k_agg    <<<agg_grid, 256>>>(h, b3, agg, 0);

    k_pool1<<<dim3(N_GRAPHS, POOL_CHUNKS), D>>>(batch);
    k_pool2<<<N_GRAPHS, D>>>(out);
}

// round 11
// speedup vs baseline: 2.2157x; 1.0019x over previous
#include <cuda_runtime.h>
#include <cuda_bf16.h>
#include <math_constants.h>
#include <cstdint>

#define N_NODES 50000
#define N_EDGES 800000
#define D 128
#define N_GRAPHS 64
#define SCAN_BLK 1024
#define N_SCAN_BLKS ((N_NODES + SCAN_BLK - 1) / SCAN_BLK)   // 49
#define POOL_CHUNKS 8

// GEMM smem layout in uint32 units, plain bf16 tiles (ldmatrix-friendly).
// W tile: 16 k-rows x 128 n bf16, row stride 68 u32 (272B = 17*16B: conflict-free)
// A tile: 128 m-rows x 16 k bf16, row stride 12 u32 (48B = 3*16B: conflict-free)
#define WSTRB 68
#define WBUFB (16 * WSTRB)       // 1088
#define ASTRB 12
#define ABUFB (128 * ASTRB)      // 1536
#define S_WH 0
#define S_WL (2 * WBUFB)                   // 2176
#define S_AH (4 * WBUFB)                   // 4352
#define S_AL (4 * WBUFB + 2 * ABUFB)       // 7424
#define S_TOT (4 * WBUFB + 4 * ABUFB)      // 10496 u32 = 41984 B

// ------------------------- device scratch ----------------------------------
__device__ float    g_dis[N_NODES];
__device__ int      g_deg[N_NODES];         // zeroed by k_scan23 for next call
__device__ int      g_rowoff[N_NODES + 1];
__device__ int      g_next[N_NODES];
__device__ int      g_bsum[N_SCAN_BLKS];
__device__ int      g_col[N_EDGES];
__device__ float    g_h[N_NODES * D];       // dis-scaled x @ W
__device__ float    g_agg[N_NODES * D];
__device__ float    g_pmax[N_GRAPHS * POOL_CHUNKS * D];
__device__ uint32_t g_Wbh[3 * 128 * 64];    // plain bf16 hi, [layer][k][n] (2n/u32)
__device__ uint32_t g_Wbl[3 * 128 * 64];    // plain bf16 lo

// ------------------------- helpers -----------------------------------------
__device__ __forceinline__ void split_pack(float x, float y,
                                           uint32_t& hi, uint32_t& lo) {
    __nv_bfloat162 h2 = __floats2bfloat162_rn(x, y);
    float rx = x - __bfloat162float(h2.x);
    float ry = y - __bfloat162float(h2.y);
    __nv_bfloat162 l2 = __floats2bfloat162_rn(rx, ry);
    hi = *reinterpret_cast<uint32_t*>(&h2);
    lo = *reinterpret_cast<uint32_t*>(&l2);
}

#define MMA_BF16(C, A0, A1, A2, A3, B0, B1)                                   \
    asm volatile(                                                             \
        "mma.sync.aligned.m16n8k16.row.col.f32.bf16.bf16.f32 "                \
        "{%0,%1,%2,%3}, {%4,%5,%6,%7}, {%8,%9}, {%0,%1,%2,%3};"               \
        : "+f"(C[0]), "+f"(C[1]), "+f"(C[2]), "+f"(C[3])                      \
        : "r"(A0), "r"(A1), "r"(A2), "r"(A3), "r"(B0), "r"(B1))

__device__ __forceinline__ void ldsm_x4(uint32_t& r0, uint32_t& r1,
                                        uint32_t& r2, uint32_t& r3,
                                        uint32_t addr) {
    asm volatile("ldmatrix.sync.aligned.m8n8.x4.shared.b16 {%0,%1,%2,%3}, [%4];"
                 : "=r"(r0), "=r"(r1), "=r"(r2), "=r"(r3) : "r"(addr));
}
__device__ __forceinline__ void ldsm_x4_t(uint32_t& r0, uint32_t& r1,
                                          uint32_t& r2, uint32_t& r3,
                                          uint32_t addr) {
    asm volatile("ldmatrix.sync.aligned.m8n8.x4.trans.shared.b16 {%0,%1,%2,%3}, [%4];"
                 : "=r"(r0), "=r"(r1), "=r"(r2), "=r"(r3) : "r"(addr));
}

__device__ __forceinline__ void cp_async16u(uint32_t* dst_smem, const uint32_t* src) {
    unsigned d = (unsigned)__cvta_generic_to_shared(dst_smem);
    asm volatile("cp.async.cg.shared.global [%0], [%1], 16;" :: "r"(d), "l"(src));
}
__device__ __forceinline__ void cp_commit() {
    asm volatile("cp.async.commit_group;");
}
__device__ __forceinline__ void cp_wait0() {
    asm volatile("cp.async.wait_group 0;");
}

// ------------------------- CSR build ---------------------------------------
__global__ void k_count(const int* __restrict__ dst) {
    int i = blockIdx.x * blockDim.x + threadIdx.x;
    if (i < N_EDGES) atomicAdd(&g_deg[dst[i]], 1);
}

__global__ __launch_bounds__(SCAN_BLK) void k_scan1() {
    __shared__ int wsum[32];
    int t = threadIdx.x;
    int lane = t & 31, warp = t >> 5;
    int i = blockIdx.x * SCAN_BLK + t;
    int v = (i < N_NODES) ? g_deg[i] : 0;
    int incl = v;
#pragma unroll
    for (int off = 1; off < 32; off <<= 1) {
        int u = __shfl_up_sync(0xffffffffu, incl, off);
        if (lane >= off) incl += u;
    }
    if (lane == 31) wsum[warp] = incl;
    __syncthreads();
    if (warp == 0) {
        int w = wsum[lane];
        int wi = w;
#pragma unroll
        for (int off = 1; off < 32; off <<= 1) {
            int u = __shfl_up_sync(0xffffffffu, wi, off);
            if (lane >= off) wi += u;
        }
        wsum[lane] = wi - w;
    }
    __syncthreads();
    int inclTot = incl + wsum[warp];
    if (i < N_NODES) {
        g_rowoff[i] = inclTot - v;
        g_dis[i] = rsqrtf((float)v + 1.0f);
    }
    if (t == SCAN_BLK - 1) g_bsum[blockIdx.x] = inclTot;
}

__global__ __launch_bounds__(SCAN_BLK) void k_scan23() {
    __shared__ int s[64];
    int t = threadIdx.x;
    if (t < 64) {
        int v = (t < N_SCAN_BLKS) ? g_bsum[t] : 0;
        s[t] = v;
        __syncthreads();
#pragma unroll
        for (int off = 1; off < 64; off <<= 1) {
            int add = (t >= off) ? s[t - off] : 0;
            __syncthreads();
            s[t] += add;
            __syncthreads();
        }
        int v2 = (t < N_SCAN_BLKS) ? g_bsum[t] : 0;
        s[t] -= v2;
    } else {
        __syncthreads();
#pragma unroll
        for (int off = 1; off < 64; off <<= 1) { __syncthreads(); __syncthreads(); }
    }
    __syncthreads();
    int boff = s[blockIdx.x];
    int i = blockIdx.x * SCAN_BLK + t;
    if (i < N_NODES) {
        int fin = g_rowoff[i] + boff;
        g_rowoff[i] = fin;
        g_next[i] = fin;
        g_deg[i] = 0;
    }
    if (i == 0) g_rowoff[N_NODES] = N_EDGES;
}

__global__ void k_fill(const int* __restrict__ src, const int* __restrict__ dst) {
    int i = blockIdx.x * blockDim.x + threadIdx.x;
    if (i < N_EDGES) {
        int pos = atomicAdd(&g_next[dst[i]], 1);
        g_col[pos] = src[i];
    }
}

// ------------------------- weight pre-split (plain bf16 hi/lo) -------------
// g_Wb*[layer*8192 + k*64 + n2] = bf16x2{ W[k][2n2], W[k][2n2+1] }
__global__ void k_splitW(const float* __restrict__ W1,
                         const float* __restrict__ W2,
                         const float* __restrict__ W3) {
    int i = blockIdx.x * blockDim.x + threadIdx.x;     // 0..24575
    if (i >= 3 * 128 * 64) return;
    int m = i >> 13, r = i & 8191;
    int k = r >> 6, n2 = r & 63;
    const float* Ws = (m == 0) ? W1 : ((m == 1) ? W2 : W3);
    float x0 = Ws[k * D + 2 * n2];
    float x1 = Ws[k * D + 2 * n2 + 1];
    uint32_t hi, lo;
    split_pack(x0, x1, hi, lo);
    g_Wbh[i] = hi;
    g_Wbl[i] = lo;
}

// ------------------------- pipelined bf16x3 GEMM with ldmatrix -------------
// 256 threads (8 warps as 4x2: M=32,N=64 per warp), M-tile 128, K chunk 16,
// double-buffered (cp.async W, register-staged A). Epilogue scales by dis[i].
__global__ __launch_bounds__(256, 2) void k_gemm_tc(const float* __restrict__ A,
                                                    const uint32_t* __restrict__ Wbh,
                                                    const uint32_t* __restrict__ Wbl,
                                                    float* __restrict__ Hout) {
    __shared__ uint32_t sm[S_TOT];
    int tid  = threadIdx.x;
    int warp = tid >> 5, lane = tid & 31;
    int g = lane >> 2, tg = lane & 3;
    int wm = warp & 3, wn = warp >> 2;          // 4x2 warp grid
    int row0 = blockIdx.x * 128;

    // copy coordinates: W chunk = 16 rows x 64 u32; one 16B cp per thread
    int wrr = tid >> 4, wcc = (tid & 15) * 4;
    // A staging: rows ar, ar+64; float col afc; u32 pair col apc
    int ar = tid >> 2;
    int afc = (tid & 3) * 4;
    int apc = (tid & 3) * 2;

    // ldmatrix lane addressing
    int rowsel = ((lane >> 3) & 1) * 8 + (lane & 7);
    int half4 = (lane >> 4) * 4;
    uint32_t smb = (uint32_t)__cvta_generic_to_shared(sm);
    // A addrs (hi; lo = +(S_AL-S_AH)*4), per mt
    uint32_t a_addr[2];
#pragma unroll
    for (int mt = 0; mt < 2; mt++)
        a_addr[mt] = smb + (uint32_t)(S_AH + (wm * 32 + mt * 16 + rowsel) * ASTRB + half4) * 4;
    // W addrs (hi; lo = +(S_WL-S_WH)*4), per n-pair p (covers nt=2p,2p+1)
    uint32_t w_addr[4];
#pragma unroll
    for (int p = 0; p < 4; p++)
        w_addr[p] = smb + (uint32_t)(S_WH + rowsel * WSTRB + wn * 32 + p * 8 + half4) * 4;

    const uint32_t ALOFF = (uint32_t)(S_AL - S_AH) * 4;
    const uint32_t WLOFF = (uint32_t)(S_WL - S_WH) * 4;

    float acc[2][8][4];
#pragma unroll
    for (int mt = 0; mt < 2; mt++)
#pragma unroll
        for (int nt = 0; nt < 8; nt++)
#pragma unroll
            for (int c = 0; c < 4; c++) acc[mt][nt][c] = 0.0f;

    // ---- prologue: stage chunk 0 into buffer 0
    cp_async16u(&sm[S_WH + wrr * WSTRB + wcc], Wbh + wrr * 64 + wcc);
    cp_async16u(&sm[S_WL + wrr * WSTRB + wcc], Wbl + wrr * 64 + wcc);
    cp_commit();
#pragma unroll
    for (int p = 0; p < 2; p++) {
        int rr = ar + p * 64;
        int gr = row0 + rr;
        float4 v = make_float4(0.f, 0.f, 0.f, 0.f);
        if (gr < N_NODES) v = *(const float4*)(A + (size_t)gr * D + afc);
        uint32_t h0, l0, h1, l1;
        split_pack(v.x, v.y, h0, l0);
        split_pack(v.z, v.w, h1, l1);
        *(uint2*)&sm[S_AH + rr * ASTRB + apc] = make_uint2(h0, h1);
        *(uint2*)&sm[S_AL + rr * ASTRB + apc] = make_uint2(l0, l1);
    }
    cp_wait0();
    __syncthreads();

    for (int kc = 0; kc < 8; kc++) {
        int buf = kc & 1, nxt = buf ^ 1;
        bool pre = (kc < 7);
        float4 v0, v1;
        if (pre) {
            const uint32_t* wh = Wbh + (kc + 1) * 1024;
            const uint32_t* wl = Wbl + (kc + 1) * 1024;
            cp_async16u(&sm[S_WH + nxt * WBUFB + wrr * WSTRB + wcc], wh + wrr * 64 + wcc);
            cp_async16u(&sm[S_WL + nxt * WBUFB + wrr * WSTRB + wcc], wl + wrr * 64 + wcc);
            cp_commit();
            int kcol = (kc + 1) * 16 + afc;
            v0 = make_float4(0.f, 0.f, 0.f, 0.f); v1 = v0;
            int gr0 = row0 + ar, gr1 = gr0 + 64;
            if (gr0 < N_NODES) v0 = *(const float4*)(A + (size_t)gr0 * D + kcol);
            if (gr1 < N_NODES) v1 = *(const float4*)(A + (size_t)gr1 * D + kcol);
        }

        // ---- MMAs on current buffer (one k16 step)
        uint32_t abufo = (uint32_t)(buf * ABUFB) * 4;
        uint32_t wbufo = (uint32_t)(buf * WBUFB) * 4;

        uint32_t ah[2][4], al[2][4];
#pragma unroll
        for (int mt = 0; mt < 2; mt++) {
            ldsm_x4(ah[mt][0], ah[mt][1], ah[mt][2], ah[mt][3], a_addr[mt] + abufo);
            ldsm_x4(al[mt][0], al[mt][1], al[mt][2], al[mt][3], a_addr[mt] + abufo + ALOFF);
        }
#pragma unroll
        for (int p = 0; p < 4; p++) {
            uint32_t bh0, bh1, bh2, bh3, bl0, bl1, bl2, bl3;
            ldsm_x4_t(bh0, bh1, bh2, bh3, w_addr[p] + wbufo);
            ldsm_x4_t(bl0, bl1, bl2, bl3, w_addr[p] + wbufo + WLOFF);
#pragma unroll
            for (int mt = 0; mt < 2; mt++) {
                MMA_BF16(acc[mt][2 * p],     ah[mt][0], ah[mt][1], ah[mt][2], ah[mt][3], bh0, bh1);
                MMA_BF16(acc[mt][2 * p],     ah[mt][0], ah[mt][1], ah[mt][2], ah[mt][3], bl0, bl1);
                MMA_BF16(acc[mt][2 * p],     al[mt][0], al[mt][1], al[mt][2], al[mt][3], bh0, bh1);
                MMA_BF16(acc[mt][2 * p + 1], ah[mt][0], ah[mt][1], ah[mt][2], ah[mt][3], bh2, bh3);
                MMA_BF16(acc[mt][2 * p + 1], ah[mt][0], ah[mt][1], ah[mt][2], ah[mt][3], bl2, bl3);
                MMA_BF16(acc[mt][2 * p + 1], al[mt][0], al[mt][1], al[mt][2], al[mt][3], bh2, bh3);
            }
        }

        if (pre) {
            uint32_t h0, l0, h1, l1;
            split_pack(v0.x, v0.y, h0, l0);
            split_pack(v0.z, v0.w, h1, l1);
            *(uint2*)&sm[S_AH + nxt * ABUFB + ar * ASTRB + apc] = make_uint2(h0, h1);
            *(uint2*)&sm[S_AL + nxt * ABUFB + ar * ASTRB + apc] = make_uint2(l0, l1);
            split_pack(v1.x, v1.y, h0, l0);
            split_pack(v1.z, v1.w, h1, l1);
            *(uint2*)&sm[S_AH + nxt * ABUFB + (ar + 64) * ASTRB + apc] = make_uint2(h0, h1);
            *(uint2*)&sm[S_AL + nxt * ABUFB + (ar + 64) * ASTRB + apc] = make_uint2(l0, l1);
            cp_wait0();
            __syncthreads();
        }
    }

    // ---- epilogue: scale row r by dis[r], store
#pragma unroll
    for (int mt = 0; mt < 2; mt++) {
        int r0 = row0 + wm * 32 + mt * 16 + g;
        int r1 = r0 + 8;
        float s0 = (r0 < N_NODES) ? g_dis[r0] : 0.f;
        float s1 = (r1 < N_NODES) ? g_dis[r1] : 0.f;
#pragma unroll
        for (int nt = 0; nt < 8; nt++) {
            int c0 = wn * 64 + nt * 8 + tg * 2;
            if (r0 < N_NODES)
                *(float2*)(Hout + (size_t)r0 * D + c0) =
                    make_float2(acc[mt][nt][0] * s0, acc[mt][nt][1] * s0);
            if (r1 < N_NODES)
                *(float2*)(Hout + (size_t)r1 * D + c0) =
                    make_float2(acc[mt][nt][2] * s1, acc[mt][nt][3] * s1);
        }
    }
}

// ------------------------- aggregation: one warp per node, MLP-8 gather ----
__global__ __launch_bounds__(256) void k_agg(const float* __restrict__ hs,
                                             const float* __restrict__ b,
                                             float* __restrict__ out,
                                             int do_relu) {
    int lane = threadIdx.x & 31;
    int node = blockIdx.x * (blockDim.x >> 5) + (threadIdx.x >> 5);
    if (node >= N_NODES) return;
    int beg = g_rowoff[node], end = g_rowoff[node + 1];
    const float4* __restrict__ h4 = (const float4*)hs;
    float4 acc = h4[(size_t)node * 32 + lane];      // self-loop term
    for (int e0 = beg; e0 < end; e0 += 32) {
        int n = min(32, end - e0);
        int c = (lane < n) ? g_col[e0 + lane] : 0;
        int j = 0;
        for (; j + 8 <= n; j += 8) {
            int cj[8];
#pragma unroll
            for (int u = 0; u < 8; u++) cj[u] = __shfl_sync(0xffffffffu, c, j + u);
            float4 hv[8];
#pragma unroll
            for (int u = 0; u < 8; u++) hv[u] = h4[(size_t)cj[u] * 32 + lane];
#pragma unroll
            for (int u = 0; u < 8; u++) {
                acc.x += hv[u].x; acc.y += hv[u].y;
                acc.z += hv[u].z; acc.w += hv[u].w;
            }
        }
        for (; j < n; j++) {
            int cj = __shfl_sync(0xffffffffu, c, j);
            float4 hv = h4[(size_t)cj * 32 + lane];
            acc.x += hv.x; acc.y += hv.y;
            acc.z += hv.z; acc.w += hv.w;
        }
    }
    float dis = g_dis[node];
    float4 bv = ((const float4*)b)[lane];
    acc.x = acc.x * dis + bv.x; acc.y = acc.y * dis + bv.y;
    acc.z = acc.z * dis + bv.z; acc.w = acc.w * dis + bv.w;
    if (do_relu) {
        acc.x = fmaxf(acc.x, 0.f); acc.y = fmaxf(acc.y, 0.f);
        acc.z = fmaxf(acc.z, 0.f); acc.w = fmaxf(acc.w, 0.f);
    }
    ((float4*)out)[(size_t)node * 32 + lane] = acc;
}

// ------------------------- pooling -----------------------------------------
__device__ __forceinline__ int lower_bound_batch(const int* __restrict__ batch, int g) {
    int lo = 0, hi = N_NODES;
    while (lo < hi) {
        int mid = (lo + hi) >> 1;
        if (batch[mid] < g) lo = mid + 1; else hi = mid;
    }
    return lo;
}

__global__ void k_pool1(const int* __restrict__ batch) {
    int g = blockIdx.x, c = blockIdx.y, t = threadIdx.x;
    int beg = lower_bound_batch(batch, g);
    int end = lower_bound_batch(batch, g + 1);
    int len = end - beg;
    int chunk = (len + POOL_CHUNKS - 1) / POOL_CHUNKS;
    int s = beg + c * chunk;
    int e = min(end, s + chunk);
    float m = -CUDART_INF_F;
    for (int r = s; r < e; r++)
        m = fmaxf(m, g_agg[(size_t)r * D + t]);
    g_pmax[(size_t)(g * POOL_CHUNKS + c) * D + t] = m;
}

__global__ void k_pool2(float* __restrict__ out) {
    int g = blockIdx.x, t = threadIdx.x;
    float m = -CUDART_INF_F;
#pragma unroll
    for (int c = 0; c < POOL_CHUNKS; c++)
        m = fmaxf(m, g_pmax[(size_t)(g * POOL_CHUNKS + c) * D + t]);
    out[(size_t)g * D + t] = m;
}

// ------------------------- launch ------------------------------------------
extern "C" void kernel_launch(void* const* d_in, const int* in_sizes, int n_in,
                              void* d_out, int out_size) {
    const float* x  = (const float*)d_in[0];
    const float* W1 = (const float*)d_in[1];
    const float* b1 = (const float*)d_in[2];
    const float* W2 = (const float*)d_in[3];
    const float* b2 = (const float*)d_in[4];
    const float* W3 = (const float*)d_in[5];
    const float* b3 = (const float*)d_in[6];
    const int* edge_index = (const int*)d_in[7];
    const int* batch = (const int*)d_in[8];
    const int* src = edge_index;
    const int* dst = edge_index + N_EDGES;
    float* out = (float*)d_out;

    float*    h   = nullptr; cudaGetSymbolAddress((void**)&h,   g_h);
    float*    agg = nullptr; cudaGetSymbolAddress((void**)&agg, g_agg);
    uint32_t* wh  = nullptr; cudaGetSymbolAddress((void**)&wh,  g_Wbh);
    uint32_t* wl  = nullptr; cudaGetSymbolAddress((void**)&wl,  g_Wbl);

    const int nthr = 256;
    const int gemm_grid = (N_NODES + 127) / 128;
    const int agg_grid  = (N_NODES + 7) / 8;
    const int WSZ = 128 * 64;   // u32 per layer

    // g_deg zero on entry: BSS-init first call, k_scan23 re-zeroes each call.
    k_count <<<(N_EDGES + nthr - 1) / nthr, nthr>>>(dst);            // 1
    k_scan1 <<<N_SCAN_BLKS, SCAN_BLK>>>();                            // 2
    k_splitW<<<(3 * WSZ + nthr - 1) / nthr, nthr>>>(W1, W2, W3);      // 3
    k_gemm_tc<<<gemm_grid, 256>>>(x, wh, wl, h);                      // 4 (profiled)
    k_scan23<<<N_SCAN_BLKS, SCAN_BLK>>>();                            // 5
    k_fill  <<<(N_EDGES + nthr - 1) / nthr, nthr>>>(src, dst);        // 6

    k_agg    <<<agg_grid, 256>>>(h, b1, agg, 1);
    k_gemm_tc<<<gemm_grid, 256>>>(agg, wh + WSZ, wl + WSZ, h);
    k_agg    <<<agg_grid, 256>>>(h, b2, agg, 1);
    k_gemm_tc<<<gemm_grid, 256>>>(agg, wh + 2 * WSZ, wl + 2 * WSZ, h);
    k_agg    <<<agg_grid, 256>>>(h, b3, agg, 0);

    k_pool1<<<dim3(N_GRAPHS, POOL_CHUNKS), D>>>(batch);
    k_pool2<<<N_GRAPHS, D>>>(out);
}